// round 13
// baseline (speedup 1.0000x reference)
#include <cuda_runtime.h>
#include <math.h>

#define NE    512
#define NH    8
#define ND    64
#define NB    2
#define NT    1024
#define NHD   512
#define NROWS 2048          // B*T
#define NFFN  2048
#define NBH   16
#define NC    16            // chunks of 64 along T
#define LDW   1664          // packed fused-proj width (1536 kqv + 24 gates + pad)

// ------------------------------ scratch (static device globals; no allocs) --
static __device__ float g_xn  [NROWS * NE];          // LN1 output
static __device__ float g_WT1 [LDW * NE];            // fused W^T [n][k]
static __device__ float g_WoT [NE * NHD];            // Wo^T  [n][k]
static __device__ float g_W1T [NFFN * NE];           // W1^T
static __device__ float g_W2T [NE * NFFN];           // W2^T
static __device__ float g_WpsT[NE * NE];             // Wps^T
static __device__ float g_bkqv[LDW];
static __device__ float g_kqv [NROWS * LDW];         // raw k|q|v|gates
static __device__ float g_coef[NROWS * NH];          // d*gw
static __device__ float g_logd[NROWS * NH];          // log(clip(d*gf))
static __device__ float g_ecum[NBH * NT];            // exp(cumsum(log decay))
static __device__ float g_invd[NBH * NT];            // 1/(ecum+1e-8)
static __device__ float g_read[NROWS * NHD];         // readout
static __device__ float g_x2  [NROWS * NE];
static __device__ float g_hh  [NROWS * NE];          // LN2 output
static __device__ float g_mid [NROWS * NFFN];        // gelu(h@W1+b1)
static __device__ float g_qn  [NBH * NC * 64 * 64];  // normalized q [j][t]
static __device__ float g_S   [NBH * NC * 64 * 64];  // per-chunk state sums
static __device__ float g_P   [NBH * NC * 64 * 64];  // exclusive prefixes

// ----------------------- generic 32x32 tiled transpose body ----------------
__device__ __forceinline__ void trans_body(const float* __restrict__ src,
                                           float* __restrict__ dst,
                                           int K, int N, int dro, int t,
                                           int tid, float* tile /*32*33*/) {
    const int ntx = (N + 31) >> 5;
    const int nb = (t % ntx) * 32, kb = (t / ntx) * 32;
    const int tx = tid & 31, ty = tid >> 5;
    #pragma unroll
    for (int i = 0; i < 4; i++) {
        const int k = kb + ty + i * 8, n = nb + tx;
        if (n < N) tile[(ty + i * 8) * 33 + tx] = src[(size_t)k * N + n];
    }
    __syncthreads();
    #pragma unroll
    for (int i = 0; i < 4; i++) {
        const int n = nb + ty + i * 8, k = kb + tx;
        if (n < N) dst[(size_t)(dro + n) * K + k] = tile[tx * 33 + ty + i * 8];
    }
}

// ------------------- single-pass LayerNorm (sum + sumsq together) ----------
__device__ __forceinline__ void ln_body(const float* __restrict__ x,
                                        const float* __restrict__ g,
                                        const float* __restrict__ b,
                                        float* __restrict__ o,
                                        int row, int tid, float* sh) {
    const float v0 = x[(size_t)row * NE + tid];
    const float v1 = x[(size_t)row * NE + tid + 256];

    float s  = v0 + v1;
    float s2 = v0 * v0 + v1 * v1;
    #pragma unroll
    for (int off = 16; off; off >>= 1) {
        s  += __shfl_xor_sync(~0u, s,  off);
        s2 += __shfl_xor_sync(~0u, s2, off);
    }
    if ((tid & 31) == 0) { sh[tid >> 5] = s; sh[8 + (tid >> 5)] = s2; }
    __syncthreads();
    if (tid < 32) {
        float t  = (tid < 8) ? sh[tid] : 0.f;
        float t2 = (tid < 8) ? sh[8 + tid] : 0.f;
        #pragma unroll
        for (int off = 4; off; off >>= 1) {
            t  += __shfl_xor_sync(~0u, t,  off);
            t2 += __shfl_xor_sync(~0u, t2, off);
        }
        if (tid == 0) { sh[0] = t; sh[8] = t2; }
    }
    __syncthreads();
    const float mu  = sh[0] * (1.f / NE);
    const float var = sh[8] * (1.f / NE) - mu * mu;
    const float inv = 1.f / sqrtf(var + 1e-5f);

    o[(size_t)row * NE + tid]       = (v0 - mu) * inv * g[tid]       + b[tid];
    o[(size_t)row * NE + tid + 256] = (v1 - mu) * inv * g[tid + 256] + b[tid + 256];
}

__global__ __launch_bounds__(256) void ln_k(const float* __restrict__ x,
                                            const float* __restrict__ g,
                                            const float* __restrict__ b,
                                            float* __restrict__ o) {
    __shared__ float sh[16];
    ln_body(x, g, b, o, blockIdx.x, threadIdx.x, sh);
}

// --- fused: LN1 (0..2047) + WT1 transposes (816) + bias/zero (208) --------
#define WT1_BLOCKS 816
__global__ __launch_bounds__(256) void ln_prep_k(
    const float* __restrict__ x, const float* __restrict__ ln1g,
    const float* __restrict__ ln1b,
    const float* __restrict__ Wk, const float* __restrict__ Wq,
    const float* __restrict__ Wv, const float* __restrict__ Wd,
    const float* __restrict__ Wgw, const float* __restrict__ Wgf,
    const float* __restrict__ bk, const float* __restrict__ bq,
    const float* __restrict__ bv, const float* __restrict__ bd,
    const float* __restrict__ bgw, const float* __restrict__ bgf) {
    __shared__ float sh[16];
    __shared__ float tile[32 * 33];
    if (blockIdx.x < NROWS) {
        ln_body(x, ln1g, ln1b, g_xn, blockIdx.x, threadIdx.x, sh);
        return;
    }
    if (blockIdx.x < NROWS + WT1_BLOCKS) {
        const int bid = blockIdx.x - NROWS;
        const float* src; int N, dro, t;
        if      (bid < 256) { src = Wk;  N = 512; dro = 0;    t = bid; }
        else if (bid < 512) { src = Wq;  N = 512; dro = 512;  t = bid - 256; }
        else if (bid < 768) { src = Wv;  N = 512; dro = 1024; t = bid - 512; }
        else if (bid < 784) { src = Wd;  N = 8;   dro = 1536; t = bid - 768; }
        else if (bid < 800) { src = Wgw; N = 8;   dro = 1544; t = bid - 784; }
        else                { src = Wgf; N = 8;   dro = 1552; t = bid - 800; }
        trans_body(src, g_WT1, 512, N, dro, t, threadIdx.x, tile);
        return;
    }
    // zero pad rows 1560..1663 of WT1 + pack biases
    const int idx = (blockIdx.x - NROWS - WT1_BLOCKS) * 256 + threadIdx.x;
    if (idx < 104 * NE) g_WT1[(size_t)1560 * NE + idx] = 0.f;
    if (idx < LDW) {
        float bb;
        if (idx < 512)        bb = bk[idx];
        else if (idx < 1024)  bb = bq[idx - 512];
        else if (idx < 1536)  bb = bv[idx - 1024];
        else if (idx < 1544)  bb = bd [idx - 1536];
        else if (idx < 1552)  bb = bgw[idx - 1544];
        else if (idx < 1560)  bb = bgf[idx - 1552];
        else                  bb = 0.f;
        g_bkqv[idx] = bb;
    }
}

// -------------------------------------------- mma + cp.async + ldmatrix ----
__device__ __forceinline__ void mma_tf32(float* d,
                                         unsigned int a0, unsigned int a1,
                                         unsigned int a2, unsigned int a3,
                                         unsigned int b0, unsigned int b1) {
    asm volatile(
        "mma.sync.aligned.m16n8k8.row.col.f32.tf32.tf32.f32 "
        "{%0,%1,%2,%3}, {%4,%5,%6,%7}, {%8,%9}, {%0,%1,%2,%3};"
        : "+f"(d[0]), "+f"(d[1]), "+f"(d[2]), "+f"(d[3])
        : "r"(a0), "r"(a1), "r"(a2), "r"(a3), "r"(b0), "r"(b1));
}

__device__ __forceinline__ void ldsm_x4(unsigned int& r0, unsigned int& r1,
                                        unsigned int& r2, unsigned int& r3,
                                        unsigned int addr) {
    asm volatile("ldmatrix.sync.aligned.m8n8.x4.shared.b16 {%0,%1,%2,%3}, [%4];"
                 : "=r"(r0), "=r"(r1), "=r"(r2), "=r"(r3) : "r"(addr));
}

__device__ __forceinline__ void cpasync16(void* s, const void* g) {
    unsigned int sa = (unsigned int)__cvta_generic_to_shared(s);
    asm volatile("cp.async.cg.shared.global [%0], [%1], 16;" :: "r"(sa), "l"(g));
}
#define CP_COMMIT()  asm volatile("cp.async.commit_group;")
#define CP_WAIT(n)   asm volatile("cp.async.wait_group %0;" :: "n"(n))

// --- tf32 tensor GEMM: C[MR,BN] tiles = A[M,K] @ Bt[N,K]^T -----------------
// MODE 1: C = v + aux1 + 0.1*aux2   MODE 2: C = gelu(v)
// MODE 3: C = v + aux1              MODE 4: C = aux1+v; C2 = aux2+v
// MODE 5: C = v, plus fused gate math on tile covering cols 1536..1663
#define KP2 36
template <int MODE, int BN, int MR>
__global__ __launch_bounds__(256, 2) void tgemm_k(
    const float* __restrict__ A, const float* __restrict__ Bt,
    const float* __restrict__ bias, float* __restrict__ C,
    int K, int ldc,
    const float* __restrict__ aux1, const float* __restrict__ aux2,
    float* __restrict__ C2) {
    constexpr int MT  = (BN == 128) ? 2 : 1;
    constexpr int NTC = (BN == 128) ? 8 : ((MR == 128) ? 8 : 4);
    constexpr int ASZ = MR * KP2;
    constexpr int BSZ = BN * KP2;
    extern __shared__ float sm[];
    float* Abuf = sm;                       // 3 stages of [MR][36]
    float* Bbuf = sm + 3 * ASZ;             // 3 stages of [BN][36]

    const int tid  = threadIdx.x;
    const int warp = tid >> 5, lane = tid & 31;
    const int g    = lane >> 2, tg = lane & 3;
    const int wm   = (BN == 128) ? (warp >> 1) : ((MR == 128) ? warp : (warp & 3));
    const int wn   = (BN == 128) ? (warp & 1)  : ((MR == 128) ? 0 : (warp >> 2));
    const int mBase = blockIdx.y * MR;
    const int nBase = blockIdx.x * BN;

    const unsigned int smA = (unsigned int)__cvta_generic_to_shared(Abuf);
    const unsigned int smB = (unsigned int)__cvta_generic_to_shared(Bbuf);

    float acc[MT][NTC][4];
    #pragma unroll
    for (int mt = 0; mt < MT; mt++)
        #pragma unroll
        for (int nt = 0; nt < NTC; nt++)
            #pragma unroll
            for (int e = 0; e < 4; e++) acc[mt][nt][e] = 0.f;

    const int nT = K >> 5;
    const int ldRow = tid >> 3, ldCh = (tid & 7) << 2;   // 32 rows per pass

    auto load_stage = [&](int t, int st) {
        const int ks = t << 5;
        float* As = Abuf + st * ASZ;
        float* Bs = Bbuf + st * BSZ;
        #pragma unroll
        for (int i = 0; i < MR / 32; i++) {
            const int row = ldRow + 32 * i;
            cpasync16(&As[row * KP2 + ldCh],
                      A + (size_t)(mBase + row) * K + ks + ldCh);
        }
        #pragma unroll
        for (int i = 0; i < BN / 32; i++) {
            const int row = ldRow + 32 * i;
            cpasync16(&Bs[row * KP2 + ldCh],
                      Bt + (size_t)(nBase + row) * K + ks + ldCh);
        }
        CP_COMMIT();
    };

    load_stage(0, 0);
    load_stage(1, 1);

    const int aRowOff = (lane & 15);
    const int aColOff = (lane >> 4) << 2;
    const int bRowOff = ((lane >> 4) << 3) + (lane & 7);
    const int bColOff = ((lane >> 3) & 1) << 2;

    int st = 0;
    for (int t = 0; t < nT; t++) {
        if (t == nT - 1) { CP_WAIT(0); } else { CP_WAIT(1); }
        __syncthreads();
        if (t + 2 < nT) {
            int st2 = st + 2; if (st2 >= 3) st2 -= 3;
            load_stage(t + 2, st2);
        }
        const unsigned int aSt = smA + (st * ASZ) * 4;
        const unsigned int bSt = smB + (st * BSZ) * 4;

        #pragma unroll
        for (int k8 = 0; k8 < 4; k8++) {
            const int kk = k8 << 3;
            unsigned int bf[NTC][2];
            #pragma unroll
            for (int ntp = 0; ntp < NTC / 2; ntp++) {
                const int n0 = wn * (NTC * 8) + ntp * 16;
                const unsigned int baddr = bSt +
                    (((n0 + bRowOff) * KP2 + kk + bColOff) << 2);
                ldsm_x4(bf[2 * ntp][0], bf[2 * ntp][1],
                        bf[2 * ntp + 1][0], bf[2 * ntp + 1][1], baddr);
            }
            #pragma unroll
            for (int mt = 0; mt < MT; mt++) {
                const int m = (BN == 128) ? (wm * 32 + mt * 16) : (wm * 16);
                unsigned int a0, a1, a2, a3;
                const unsigned int aaddr = aSt +
                    (((m + aRowOff) * KP2 + kk + aColOff) << 2);
                ldsm_x4(a0, a1, a2, a3, aaddr);
                #pragma unroll
                for (int nt = 0; nt < NTC; nt++)
                    mma_tf32(acc[mt][nt], a0, a1, a2, a3, bf[nt][0], bf[nt][1]);
            }
        }
        if (++st >= 3) st -= 3;
    }

    #pragma unroll
    for (int mt = 0; mt < MT; mt++) {
        const int r0 = mBase + ((BN == 128) ? (wm * 32 + mt * 16) : (wm * 16)) + g;
        const int r1 = r0 + 8;
        #pragma unroll
        for (int nt = 0; nt < NTC; nt++) {
            const int col = nBase + wn * (NTC * 8) + nt * 8 + 2 * tg;
            const float b0 = bias[col], b1 = bias[col + 1];
            float e00 = acc[mt][nt][0] + b0, e01 = acc[mt][nt][1] + b1;
            float e10 = acc[mt][nt][2] + b0, e11 = acc[mt][nt][3] + b1;
            const size_t i0 = (size_t)r0 * ldc + col;
            const size_t i1 = (size_t)r1 * ldc + col;
            if (MODE == 5) {
                *(float2*)&C[i0] = make_float2(e00, e01);
                *(float2*)&C[i1] = make_float2(e10, e11);
            } else if (MODE == 1) {
                const float2 a0v = *(const float2*)&aux1[i0];
                const float2 a1v = *(const float2*)&aux1[i1];
                const float2 m0v = *(const float2*)&aux2[i0];
                const float2 m1v = *(const float2*)&aux2[i1];
                *(float2*)&C[i0] = make_float2(e00 + a0v.x + 0.1f * m0v.x,
                                               e01 + a0v.y + 0.1f * m0v.y);
                *(float2*)&C[i1] = make_float2(e10 + a1v.x + 0.1f * m1v.x,
                                               e11 + a1v.y + 0.1f * m1v.y);
            } else if (MODE == 2) {
                e00 = 0.5f * e00 * (1.f + erff(e00 * 0.7071067811865475f));
                e01 = 0.5f * e01 * (1.f + erff(e01 * 0.7071067811865475f));
                e10 = 0.5f * e10 * (1.f + erff(e10 * 0.7071067811865475f));
                e11 = 0.5f * e11 * (1.f + erff(e11 * 0.7071067811865475f));
                *(float2*)&C[i0] = make_float2(e00, e01);
                *(float2*)&C[i1] = make_float2(e10, e11);
            } else if (MODE == 3) {
                const float2 a0v = *(const float2*)&aux1[i0];
                const float2 a1v = *(const float2*)&aux1[i1];
                *(float2*)&C[i0] = make_float2(e00 + a0v.x, e01 + a0v.y);
                *(float2*)&C[i1] = make_float2(e10 + a1v.x, e11 + a1v.y);
            } else {
                const float2 p0 = *(const float2*)&aux1[i0];
                const float2 p1 = *(const float2*)&aux1[i1];
                const float2 q0 = *(const float2*)&aux2[i0];
                const float2 q1 = *(const float2*)&aux2[i1];
                *(float2*)&C[i0]  = make_float2(p0.x + e00, p0.y + e01);
                *(float2*)&C[i1]  = make_float2(p1.x + e10, p1.y + e11);
                *(float2*)&C2[i0] = make_float2(q0.x + e00, q0.y + e01);
                *(float2*)&C2[i1] = make_float2(q1.x + e10, q1.y + e11);
            }
        }
    }

    // -------- fused gate math (MODE 5, block covering cols 1536..1663) -----
    if (MODE == 5 && nBase == 1536) {
        __syncthreads();     // make this block's global C writes visible
        #pragma unroll
        for (int u = 0; u < 4; u++) {
            const int idx = u * 256 + tid;          // 0..1023 = 128 rows x 8 h
            const int row = mBase + (idx >> 3), h = idx & 7;
            const float* gp = C + (size_t)row * ldc + 1536;
            const float xd = gp[h], xgw = gp[8 + h], xgf = gp[16 + h];
            const float d  = fmaxf(xd, 0.f) + log1pf(expf(-fabsf(xd)));
            const float sw = 1.f / (1.f + expf(-xgw));
            const float sf = 1.f / (1.f + expf(-xgf));
            g_coef[row * NH + h] = d * (sw * sw);
            const float dec = fminf(fmaxf(d * (1.f - sf * sf), 1e-6f), 0.999f);
            g_logd[row * NH + h] = logf(dec);
        }
    }
}

// ------- cumsum of log-decay: two-level serial (64 chunks of 16) -----------
__global__ __launch_bounds__(64) void cumsum_k() {
    __shared__ float csum[64];
    const int bh = blockIdx.x, b = bh >> 3, h = bh & 7;
    const int tid = threadIdx.x;
    const int t0 = tid * 16;

    float v[16];
    float acc = 0.f;
    #pragma unroll
    for (int i = 0; i < 16; i++) {
        acc += g_logd[(b * NT + t0 + i) * NH + h];
        v[i] = acc;
    }
    csum[tid] = acc;
    __syncthreads();
    if (tid == 0) {
        float a = 0.f;
        #pragma unroll
        for (int j = 0; j < 64; j++) {
            const float t = csum[j];
            csum[j] = a;
            a += t;
        }
    }
    __syncthreads();
    const float base = csum[tid];
    #pragma unroll
    for (int i = 0; i < 16; i++) {
        const float e = expf(base + v[i]);   // underflows to 0 like the ref
        g_ecum[bh * NT + t0 + i] = e;
        g_invd[bh * NT + t0 + i] = 1.f / (e + 1e-8f);
    }
}

// 4x4 outer-product accumulate: acc[a][c] += q[a] * p[c] (float4 components)
#define OP16(acc, q, p) do {                                                  \
    acc[0][0] = fmaf((q).x, (p).x, acc[0][0]);                                \
    acc[0][1] = fmaf((q).x, (p).y, acc[0][1]);                                \
    acc[0][2] = fmaf((q).x, (p).z, acc[0][2]);                                \
    acc[0][3] = fmaf((q).x, (p).w, acc[0][3]);                                \
    acc[1][0] = fmaf((q).y, (p).x, acc[1][0]);                                \
    acc[1][1] = fmaf((q).y, (p).y, acc[1][1]);                                \
    acc[1][2] = fmaf((q).y, (p).z, acc[1][2]);                                \
    acc[1][3] = fmaf((q).y, (p).w, acc[1][3]);                                \
    acc[2][0] = fmaf((q).z, (p).x, acc[2][0]);                                \
    acc[2][1] = fmaf((q).z, (p).y, acc[2][1]);                                \
    acc[2][2] = fmaf((q).z, (p).z, acc[2][2]);                                \
    acc[2][3] = fmaf((q).z, (p).w, acc[2][3]);                                \
    acc[3][0] = fmaf((q).w, (p).x, acc[3][0]);                                \
    acc[3][1] = fmaf((q).w, (p).y, acc[3][1]);                                \
    acc[3][2] = fmaf((q).w, (p).z, acc[3][2]);                                \
    acc[3][3] = fmaf((q).w, (p).w, acc[3][3]);                                \
} while (0)

// ===== scan phase 1 (bx < NC) + fused big-weight transposes (bx >= NC) =====
#define SP 68
#define XTRA_X 160          // 160*16 = 2560 transpose blocks
__global__ __launch_bounds__(256, 3) void scan_p1(
    const float* __restrict__ Wo, const float* __restrict__ W1,
    const float* __restrict__ W2, const float* __restrict__ Wps) {
    extern __shared__ float sm[];
    if (blockIdx.x >= NC) {
        // transpose worker: Wo(256) | W1(1024) | W2(1024) | Wps(256)
        const int id = (blockIdx.x - NC) * 16 + blockIdx.y;
        const float* src; float* dst; int K, N, t;
        if      (id < 256)  { src = Wo;  dst = g_WoT;  K = 512;  N = 512;  t = id; }
        else if (id < 1280) { src = W1;  dst = g_W1T;  K = 512;  N = 2048; t = id - 256; }
        else if (id < 2304) { src = W2;  dst = g_W2T;  K = 2048; N = 512;  t = id - 1280; }
        else                { src = Wps; dst = g_WpsT; K = 512;  N = 512;  t = id - 2304; }
        trans_body(src, dst, K, N, 0, t, threadIdx.x, sm);
        return;
    }
    float* sK = sm;                  // [t][j]  -> [j][s] (Kt) -> [s][t] (Gt)
    float* sQ = sm + 64 * SP;        // [t][j]  -> [j][t] (Qt)
    float* sA = sm + 2 * 64 * SP;    // [s][i]
    float* es = sm + 3 * 64 * SP;    // [64]
    const int tc = blockIdx.x, bh = blockIdx.y, b = bh >> 3, h = bh & 7;
    const int tid = threadIdx.x;

    #pragma unroll
    for (int f = 0; f < 4; f++) {
        const int e4 = f * 256 + tid;
        const int tt = e4 >> 4, j4 = (e4 & 15) << 2;
        const int row = b * NT + tc * 64 + tt;
        const float* rp = g_kqv + (size_t)row * LDW + h * 64;
        *(float4*)&sK[tt * SP + j4] = *(const float4*)(rp + j4);
        *(float4*)&sQ[tt * SP + j4] = *(const float4*)(rp + 512 + j4);
        const float4 v = *(const float4*)(rp + 1024 + j4);
        const float sc = g_coef[row * NH + h] * g_invd[bh * NT + tc * 64 + tt];
        float4 a4;
        a4.x = tanhf(v.x) * sc; a4.y = tanhf(v.y) * sc;
        a4.z = tanhf(v.z) * sc; a4.w = tanhf(v.w) * sc;
        *(float4*)&sA[tt * SP + j4] = a4;
    }
    if (tid < 64) es[tid] = g_ecum[bh * NT + tc * 64 + tid];
    __syncthreads();

    {
        const int nr = tid >> 2, nq = tid & 3;
        float sk = 0.f, sq = 0.f;
        #pragma unroll
        for (int e = 0; e < 16; e++) {
            const float kv = sK[nr * SP + nq * 16 + e];
            const float qv = sQ[nr * SP + nq * 16 + e];
            sk = fmaf(kv, kv, sk);
            sq = fmaf(qv, qv, sq);
        }
        sk += __shfl_xor_sync(~0u, sk, 1); sk += __shfl_xor_sync(~0u, sk, 2);
        sq += __shfl_xor_sync(~0u, sq, 1); sq += __shfl_xor_sync(~0u, sq, 2);
        const float ik = 1.f / fmaxf(sqrtf(sk), 1e-12f);
        const float iq = 1.f / fmaxf(sqrtf(sq), 1e-12f);
        #pragma unroll
        for (int e = 0; e < 16; e++) {
            sK[nr * SP + nq * 16 + e] *= ik;
            sQ[nr * SP + nq * 16 + e] *= iq;
        }
    }
    __syncthreads();

    // S_c[i][j] = sum_s A[s][i] * K[s][j]
    {
        const int i4 = (tid & 15) * 4, j4 = (tid >> 4) * 4;
        float acc[4][4];
        #pragma unroll
        for (int a = 0; a < 4; a++)
            #pragma unroll
            for (int c = 0; c < 4; c++) acc[a][c] = 0.f;
        for (int s = 0; s < 64; s++) {
            const float4 av = *(const float4*)&sA[s * SP + i4];
            const float4 kv = *(const float4*)&sK[s * SP + j4];
            OP16(acc, av, kv);
        }
        float* Sp = g_S + ((size_t)bh * NC + tc) * 4096;
        #pragma unroll
        for (int a = 0; a < 4; a++)
            #pragma unroll
            for (int c = 0; c < 4; c++) Sp[(i4 + a) * 64 + j4 + c] = acc[a][c];
    }

    // in-place transpose Q then K
    float4 qr[4];
    {
        #pragma unroll
        for (int f = 0; f < 4; f++) {
            const int e4 = f * 256 + tid;
            const int tt = e4 >> 4, j4 = (e4 & 15) << 2;
            qr[f] = *(const float4*)&sQ[tt * SP + j4];
        }
    }
    __syncthreads();
    {
        float4 kr[4];
        #pragma unroll
        for (int f = 0; f < 4; f++) {
            const int e4 = f * 256 + tid;
            const int tt = e4 >> 4, j4 = (e4 & 15) << 2;
            sQ[(j4 + 0) * SP + tt] = qr[f].x;
            sQ[(j4 + 1) * SP + tt] = qr[f].y;
            sQ[(j4 + 2) * SP + tt] = qr[f].z;
            sQ[(j4 + 3) * SP + tt] = qr[f].w;
            kr[f] = *(const float4*)&sK[tt * SP + j4];
        }
        __syncthreads();
        #pragma unroll
        for (int f = 0; f < 4; f++) {
            const int e4 = f * 256 + tid;
            const int tt = e4 >> 4, j4 = (e4 & 15) << 2;
            sK[(j4 + 0) * SP + tt] = kr[f].x;
            sK[(j4 + 1) * SP + tt] = kr[f].y;
            sK[(j4 + 2) * SP + tt] = kr[f].z;
            sK[(j4 + 3) * SP + tt] = kr[f].w;
        }
    }
    __syncthreads();

    // export normalized Q transposed [j][t] for phase 3
    #pragma unroll
    for (int f = 0; f < 4; f++) {
        const int e4 = f * 256 + tid;
        const int jj = e4 >> 4, t4 = (e4 & 15) << 2;
        *(float4*)&g_qn[(((size_t)bh * NC + tc) * 64 + jj) * 64 + t4] =
            *(const float4*)&sQ[jj * SP + t4];
    }

    // G[t][s] (causal) from Qt/Kt; overwrite sK with Gt[s][t]
    {
        const int t4 = (tid & 15) * 4, s4 = (tid >> 4) * 4;
        float acc[4][4];
        #pragma unroll
        for (int a = 0; a < 4; a++)
            #pragma unroll
            for (int c = 0; c < 4; c++) acc[a][c] = 0.f;
        if (s4 <= t4 + 3) {
            for (int j = 0; j < 64; j++) {
                const float4 qv = *(const float4*)&sQ[j * SP + t4];
                const float4 kv = *(const float4*)&sK[j * SP + s4];
                OP16(acc, qv, kv);
            }
        }
        __syncthreads();
        #pragma unroll
        for (int c = 0; c < 4; c++) {
            float4 o;
            o.x = (s4 + c <= t4 + 0) ? acc[0][c] : 0.f;
            o.y = (s4 + c <= t4 + 1) ? acc[1][c] : 0.f;
            o.z = (s4 + c <= t4 + 2) ? acc[2][c] : 0.f;
            o.w = (s4 + c <= t4 + 3) ? acc[3][c] : 0.f;
            *(float4*)&sK[(s4 + c) * SP + t4] = o;
        }
    }
    __syncthreads();

    // r_local[t][i] = sum_{s<=t} G[t][s] * A[s][i]; store es_t * r_local
    {
        const int t4 = (tid & 15) * 4, i4 = (tid >> 4) * 4;
        float acc[4][4];
        #pragma unroll
        for (int a = 0; a < 4; a++)
            #pragma unroll
            for (int c = 0; c < 4; c++) acc[a][c] = 0.f;
        const int smax = t4 + 4;
        for (int s = 0; s < smax; s++) {
            const float4 gv = *(const float4*)&sK[s * SP + t4];
            const float4 av = *(const float4*)&sA[s * SP + i4];
            OP16(acc, gv, av);
        }
        #pragma unroll
        for (int a = 0; a < 4; a++) {
            const float e = es[t4 + a];
            const size_t ro = (size_t)(b * NT + tc * 64 + t4 + a) * NHD + h * 64;
            #pragma unroll
            for (int c = 0; c < 4; c++) g_read[ro + i4 + c] = e * acc[a][c];
        }
    }
}

// ============ phase 2: exclusive prefix of chunk sums + next_mem ===========
__global__ __launch_bounds__(256) void scan_p2(float* __restrict__ next_mem) {
    const int bh = blockIdx.x;
    const int e  = blockIdx.y * 256 + threadIdx.x;      // 0..4095
    const float elast = g_ecum[bh * NT + NT - 1];
    float acc = 0.f;
    #pragma unroll
    for (int c = 0; c < NC; c++) {
        g_P[((size_t)bh * NC + c) * 4096 + e] = acc;
        acc += g_S[((size_t)bh * NC + c) * 4096 + e];
    }
    next_mem[(size_t)bh * 4096 + e] = acc * elast;
}

// ============ phase 3: cross term r += es_t * (P_{c-1} q_t) ================
__global__ __launch_bounds__(256) void scan_p3() {
    __shared__ float sQt[64 * SP];
    __shared__ float sPt[64 * SP];
    __shared__ float es[64];
    const int tc = blockIdx.x + 1, bh = blockIdx.y, b = bh >> 3, h = bh & 7;
    const int tid = threadIdx.x;
    #pragma unroll
    for (int f = 0; f < 4; f++) {
        const int e4 = f * 256 + tid;
        const int r = e4 >> 4, c4 = (e4 & 15) << 2;
        *(float4*)&sQt[r * SP + c4] =
            *(const float4*)&g_qn[(((size_t)bh * NC + tc) * 64 + r) * 64 + c4];
        const float4 p =
            *(const float4*)&g_P[((size_t)bh * NC + tc) * 4096 + r * 64 + c4];
        sPt[(c4 + 0) * SP + r] = p.x; sPt[(c4 + 1) * SP + r] = p.y;
        sPt[(c4 + 2) * SP + r] = p.z; sPt[(c4 + 3) * SP + r] = p.w;
    }
    if (tid < 64) es[tid] = g_ecum[bh * NT + tc * 64 + tid];
    __syncthreads();

    const int t4 = (tid & 15) * 4, i4 = (tid >> 4) * 4;
    float acc[4][4];
    #pragma unroll
    for (int a = 0; a < 4; a++)
        #pragma unroll
        for (int c = 0; c < 4; c++) acc[a][c] = 0.f;
    for (int j = 0; j < 64; j++) {
        const float4 qv = *(const float4*)&sQt[j * SP + t4];
        const float4 pv = *(const float4*)&sPt[j * SP + i4];
        OP16(acc, qv, pv);
    }
    #pragma unroll
    for (int a = 0; a < 4; a++) {
        const float e = es[t4 + a];
        const size_t ro = (size_t)(b * NT + tc * 64 + t4 + a) * NHD + h * 64;
        #pragma unroll
        for (int c = 0; c < 4; c++) g_read[ro + i4 + c] += e * acc[a][c];
    }
}

// ---------------------------------------------------------------- launch ---
static float* sym(const void* s) {
    void* p = nullptr;
    cudaGetSymbolAddress(&p, s);
    return (float*)p;
}

extern "C" void kernel_launch(void* const* d_in, const int* in_sizes, int n_in,
                              void* d_out, int out_size) {
    const float* x     = (const float*)d_in[0];
    const float* b_min = (const float*)d_in[1];
    const float* b_max = (const float*)d_in[2];
    const float* motif = (const float*)d_in[3];
    const float* Wk    = (const float*)d_in[4];
    const float* bk    = (const float*)d_in[5];
    const float* Wq    = (const float*)d_in[6];
    const float* bq    = (const float*)d_in[7];
    const float* Wv    = (const float*)d_in[8];
    const float* bv    = (const float*)d_in[9];
    const float* Wo    = (const float*)d_in[10];
    const float* bo    = (const float*)d_in[11];
    const float* Wd    = (const float*)d_in[12];
    const float* bd    = (const float*)d_in[13];
    const float* Wgw   = (const float*)d_in[14];
    const float* bgw   = (const float*)d_in[15];
    const float* Wgf   = (const float*)d_in[16];
    const float* bgf   = (const float*)d_in[17];
    const float* Wps   = (const float*)d_in[18];
    const float* bps   = (const float*)d_in[19];
    const float* ln1g  = (const float*)d_in[20];
    const float* ln1b  = (const float*)d_in[21];
    const float* ln2g  = (const float*)d_in[22];
    const float* ln2b  = (const float*)d_in[23];
    const float* W1    = (const float*)d_in[24];
    const float* b1    = (const float*)d_in[25];
    const float* W2    = (const float*)d_in[26];
    const float* b2    = (const float*)d_in[27];

    float* out    = (float*)d_out;
    float* out_x3 = out;                            // [2,1024,512]
    float* out_nm = out + (size_t)NROWS * NE;       // [2,8,64,64]
    float* out_pm = out_nm + NBH * ND * ND;         // b_min + probe
    float* out_px = out_pm + (size_t)NROWS * NE;    // b_max + probe

    float* xn   = sym(g_xn);
    float* WT1  = sym(g_WT1);
    float* WoT  = sym(g_WoT);
    float* W1T  = sym(g_W1T);
    float* W2T  = sym(g_W2T);
    float* WpsT = sym(g_WpsT);
    float* bkqv = sym(g_bkqv);
    float* kqv  = sym(g_kqv);
    float* rd   = sym(g_read);
    float* x2   = sym(g_x2);
    float* hh   = sym(g_hh);
    float* mid  = sym(g_mid);

    const int SM128 = 3 * (128 * KP2 + 128 * KP2) * 4;   // 110592
    const int SM64  = 3 * (64 * KP2 + 64 * KP2)   * 4;   // 55296
    const int SMP1  = (3 * 64 * SP + 64) * 4;            // 52480
    cudaFuncSetAttribute(tgemm_k<5,128,128>, cudaFuncAttributeMaxDynamicSharedMemorySize, SM128);
    cudaFuncSetAttribute(tgemm_k<2,128,128>, cudaFuncAttributeMaxDynamicSharedMemorySize, SM128);
    cudaFuncSetAttribute(tgemm_k<1,64,64>,   cudaFuncAttributeMaxDynamicSharedMemorySize, SM64);
    cudaFuncSetAttribute(tgemm_k<3,64,64>,   cudaFuncAttributeMaxDynamicSharedMemorySize, SM64);
    cudaFuncSetAttribute(tgemm_k<4,64,64>,   cudaFuncAttributeMaxDynamicSharedMemorySize, SM64);
    cudaFuncSetAttribute(scan_p1,            cudaFuncAttributeMaxDynamicSharedMemorySize, SMP1);

    // fused: LN1 + WT1 transposes + bias/zero (critical-path minimum)
    const int ZB_BLOCKS = (104 * NE + 255) / 256;        // 208
    ln_prep_k<<<NROWS + WT1_BLOCKS + ZB_BLOCKS, 256>>>(
        x, ln1g, ln1b, Wk, Wq, Wv, Wd, Wgw, Wgf,
        bk, bq, bv, bd, bgw, bgf);                                             // 0
    tgemm_k<5,128,128><<<dim3(13, 16), 256, SM128>>>(xn, WT1, bkqv, kqv,
                                                     512, LDW,
                                                     nullptr, nullptr, nullptr);// 1
    cumsum_k<<<NBH, 64>>>();                                                   // 2
    // scan + big-weight transposes fused (transposes finish before consumers)
    scan_p1<<<dim3(NC + XTRA_X, NBH), 256, SMP1>>>(Wo, W1, W2, Wps);           // 3
    scan_p2<<<dim3(NBH, 16), 256>>>(out_nm);                                   // 4
    scan_p3<<<dim3(NC - 1, NBH), 256>>>();                                     // 5

    tgemm_k<1,64,64><<<dim3(8, 32), 256, SM64>>>(rd, WoT, bo, x2, 512, 512,
                                                 x, motif, nullptr);           // 6
    ln_k<<<NROWS, 256>>>(x2, ln2g, ln2b, hh);                                  // 7
    tgemm_k<2,128,128><<<dim3(16, 16), 256, SM128>>>(hh, W1T, b1, mid,
                                                     512, 2048,
                                                     nullptr, nullptr, nullptr);// 8
    tgemm_k<3,64,64><<<dim3(8, 32), 256, SM64>>>(mid, W2T, b2, out_x3,
                                                 2048, 512,
                                                 x2, nullptr, nullptr);        // 9
    tgemm_k<4,64,64><<<dim3(8, 32), 256, SM64>>>(out_x3, WpsT, bps, out_pm,
                                                 512, 512,
                                                 b_min, b_max, out_px);        // 10
}

// round 14
// speedup vs baseline: 1.0809x; 1.0809x over previous
#include <cuda_runtime.h>
#include <math.h>

#define NE    512
#define NH    8
#define ND    64
#define NB    2
#define NT    1024
#define NHD   512
#define NROWS 2048          // B*T
#define NFFN  2048
#define NBH   16
#define NC    16            // chunks of 64 along T
#define LDW   1664          // packed fused-proj width (1536 kqv + 24 gates + pad)

// ------------------------------ scratch (static device globals; no allocs) --
static __device__ float g_xn  [NROWS * NE];          // LN1 output
static __device__ float g_WT1 [LDW * NE];            // fused W^T [n][k]
static __device__ float g_WoT [NE * NHD];            // Wo^T  [n][k]
static __device__ float g_W1T [NFFN * NE];           // W1^T
static __device__ float g_W2T [NE * NFFN];           // W2^T
static __device__ float g_WpsT[NE * NE];             // Wps^T
static __device__ float g_bkqv[LDW];
static __device__ float g_kqv [NROWS * LDW];         // raw k|q|v|gates
static __device__ float g_coef[NROWS * NH];          // d*gw
static __device__ float g_logd[NROWS * NH];          // log(clip(d*gf))
static __device__ float g_ecum[NBH * NT];            // exp(cumsum(log decay))
static __device__ float g_invd[NBH * NT];            // 1/(ecum+1e-8)
static __device__ float g_read[NROWS * NHD];         // readout
static __device__ float g_x2  [NROWS * NE];
static __device__ float g_hh  [NROWS * NE];          // LN2 output
static __device__ float g_mid [NROWS * NFFN];        // gelu(h@W1+b1)
static __device__ float g_qn  [NBH * NC * 64 * 64];  // normalized q [j][t]
static __device__ float g_S   [NBH * NC * 64 * 64];  // per-chunk state sums
static __device__ float g_P   [NBH * NC * 64 * 64];  // exclusive prefixes

// ----------------------- generic 32x32 tiled transpose body ----------------
__device__ __forceinline__ void trans_body(const float* __restrict__ src,
                                           float* __restrict__ dst,
                                           int K, int N, int dro, int t,
                                           int tid, float* tile /*32*33*/) {
    const int ntx = (N + 31) >> 5;
    const int nb = (t % ntx) * 32, kb = (t / ntx) * 32;
    const int tx = tid & 31, ty = tid >> 5;
    #pragma unroll
    for (int i = 0; i < 4; i++) {
        const int k = kb + ty + i * 8, n = nb + tx;
        if (n < N) tile[(ty + i * 8) * 33 + tx] = src[(size_t)k * N + n];
    }
    __syncthreads();
    #pragma unroll
    for (int i = 0; i < 4; i++) {
        const int n = nb + ty + i * 8, k = kb + tx;
        if (n < N) dst[(size_t)(dro + n) * K + k] = tile[tx * 33 + ty + i * 8];
    }
}

// ------------------- single-pass LayerNorm (sum + sumsq together) ----------
__device__ __forceinline__ void ln_body(const float* __restrict__ x,
                                        const float* __restrict__ g,
                                        const float* __restrict__ b,
                                        float* __restrict__ o,
                                        int row, int tid, float* sh) {
    const float v0 = x[(size_t)row * NE + tid];
    const float v1 = x[(size_t)row * NE + tid + 256];

    float s  = v0 + v1;
    float s2 = v0 * v0 + v1 * v1;
    #pragma unroll
    for (int off = 16; off; off >>= 1) {
        s  += __shfl_xor_sync(~0u, s,  off);
        s2 += __shfl_xor_sync(~0u, s2, off);
    }
    if ((tid & 31) == 0) { sh[tid >> 5] = s; sh[8 + (tid >> 5)] = s2; }
    __syncthreads();
    if (tid < 32) {
        float t  = (tid < 8) ? sh[tid] : 0.f;
        float t2 = (tid < 8) ? sh[8 + tid] : 0.f;
        #pragma unroll
        for (int off = 4; off; off >>= 1) {
            t  += __shfl_xor_sync(~0u, t,  off);
            t2 += __shfl_xor_sync(~0u, t2, off);
        }
        if (tid == 0) { sh[0] = t; sh[8] = t2; }
    }
    __syncthreads();
    const float mu  = sh[0] * (1.f / NE);
    const float var = sh[8] * (1.f / NE) - mu * mu;
    const float inv = 1.f / sqrtf(var + 1e-5f);

    o[(size_t)row * NE + tid]       = (v0 - mu) * inv * g[tid]       + b[tid];
    o[(size_t)row * NE + tid + 256] = (v1 - mu) * inv * g[tid + 256] + b[tid + 256];
}

__global__ __launch_bounds__(256) void ln_k(const float* __restrict__ x,
                                            const float* __restrict__ g,
                                            const float* __restrict__ b,
                                            float* __restrict__ o) {
    __shared__ float sh[16];
    ln_body(x, g, b, o, blockIdx.x, threadIdx.x, sh);
}

// --- fused: LN1 (0..2047) + ALL weight transposes (3376) + bias/zero -------
#define TRANS_BLOCKS 3376
__global__ __launch_bounds__(256) void ln_prep_k(
    const float* __restrict__ x, const float* __restrict__ ln1g,
    const float* __restrict__ ln1b,
    const float* __restrict__ Wk, const float* __restrict__ Wq,
    const float* __restrict__ Wv, const float* __restrict__ Wd,
    const float* __restrict__ Wgw, const float* __restrict__ Wgf,
    const float* __restrict__ Wo, const float* __restrict__ W1,
    const float* __restrict__ W2, const float* __restrict__ Wps,
    const float* __restrict__ bk, const float* __restrict__ bq,
    const float* __restrict__ bv, const float* __restrict__ bd,
    const float* __restrict__ bgw, const float* __restrict__ bgf) {
    __shared__ float sh[16];
    __shared__ float tile[32 * 33];
    if (blockIdx.x < NROWS) {
        ln_body(x, ln1g, ln1b, g_xn, blockIdx.x, threadIdx.x, sh);
        return;
    }
    if (blockIdx.x < NROWS + TRANS_BLOCKS) {
        const int bid = blockIdx.x - NROWS;
        const float* src; float* dst; int K, N, dro, t;
        if      (bid < 256)  { src = Wk;  dst = g_WT1;  K = 512;  N = 512;  dro = 0;    t = bid; }
        else if (bid < 512)  { src = Wq;  dst = g_WT1;  K = 512;  N = 512;  dro = 512;  t = bid - 256; }
        else if (bid < 768)  { src = Wv;  dst = g_WT1;  K = 512;  N = 512;  dro = 1024; t = bid - 512; }
        else if (bid < 784)  { src = Wd;  dst = g_WT1;  K = 512;  N = 8;    dro = 1536; t = bid - 768; }
        else if (bid < 800)  { src = Wgw; dst = g_WT1;  K = 512;  N = 8;    dro = 1544; t = bid - 784; }
        else if (bid < 816)  { src = Wgf; dst = g_WT1;  K = 512;  N = 8;    dro = 1552; t = bid - 800; }
        else if (bid < 1072) { src = Wo;  dst = g_WoT;  K = 512;  N = 512;  dro = 0;    t = bid - 816; }
        else if (bid < 2096) { src = W1;  dst = g_W1T;  K = 512;  N = 2048; dro = 0;    t = bid - 1072; }
        else if (bid < 3120) { src = W2;  dst = g_W2T;  K = 2048; N = 512;  dro = 0;    t = bid - 2096; }
        else                 { src = Wps; dst = g_WpsT; K = 512;  N = 512;  dro = 0;    t = bid - 3120; }
        trans_body(src, dst, K, N, dro, t, threadIdx.x, tile);
        return;
    }
    // zero pad rows 1560..1663 of WT1 + pack biases
    const int idx = (blockIdx.x - NROWS - TRANS_BLOCKS) * 256 + threadIdx.x;
    if (idx < 104 * NE) g_WT1[(size_t)1560 * NE + idx] = 0.f;
    if (idx < LDW) {
        float bb;
        if (idx < 512)        bb = bk[idx];
        else if (idx < 1024)  bb = bq[idx - 512];
        else if (idx < 1536)  bb = bv[idx - 1024];
        else if (idx < 1544)  bb = bd [idx - 1536];
        else if (idx < 1552)  bb = bgw[idx - 1544];
        else if (idx < 1560)  bb = bgf[idx - 1552];
        else                  bb = 0.f;
        g_bkqv[idx] = bb;
    }
}

// -------------------------------------------- mma + cp.async + ldmatrix ----
__device__ __forceinline__ void mma_tf32(float* d,
                                         unsigned int a0, unsigned int a1,
                                         unsigned int a2, unsigned int a3,
                                         unsigned int b0, unsigned int b1) {
    asm volatile(
        "mma.sync.aligned.m16n8k8.row.col.f32.tf32.tf32.f32 "
        "{%0,%1,%2,%3}, {%4,%5,%6,%7}, {%8,%9}, {%0,%1,%2,%3};"
        : "+f"(d[0]), "+f"(d[1]), "+f"(d[2]), "+f"(d[3])
        : "r"(a0), "r"(a1), "r"(a2), "r"(a3), "r"(b0), "r"(b1));
}

__device__ __forceinline__ void ldsm_x4(unsigned int& r0, unsigned int& r1,
                                        unsigned int& r2, unsigned int& r3,
                                        unsigned int addr) {
    asm volatile("ldmatrix.sync.aligned.m8n8.x4.shared.b16 {%0,%1,%2,%3}, [%4];"
                 : "=r"(r0), "=r"(r1), "=r"(r2), "=r"(r3) : "r"(addr));
}

__device__ __forceinline__ void cpasync16(void* s, const void* g) {
    unsigned int sa = (unsigned int)__cvta_generic_to_shared(s);
    asm volatile("cp.async.cg.shared.global [%0], [%1], 16;" :: "r"(sa), "l"(g));
}
#define CP_COMMIT()  asm volatile("cp.async.commit_group;")
#define CP_WAIT(n)   asm volatile("cp.async.wait_group %0;" :: "n"(n))

// --- tf32 tensor GEMM: C[MR,BN] tiles = A[M,K] @ Bt[N,K]^T -----------------
// MODE 1: C = v + aux1 + 0.1*aux2   MODE 2: C = gelu(v)
// MODE 3: C = v + aux1              MODE 4: C = aux1+v; C2 = aux2+v
// MODE 5: C = v, plus fused gate math on tile covering cols 1536..1663
#define KP2 36
template <int MODE, int BN, int MR>
__global__ __launch_bounds__(256, 2) void tgemm_k(
    const float* __restrict__ A, const float* __restrict__ Bt,
    const float* __restrict__ bias, float* __restrict__ C,
    int K, int ldc,
    const float* __restrict__ aux1, const float* __restrict__ aux2,
    float* __restrict__ C2) {
    constexpr int MT  = (BN == 128) ? 2 : 1;
    constexpr int NTC = (BN == 128) ? 8 : ((MR == 128) ? 8 : 4);
    constexpr int ASZ = MR * KP2;
    constexpr int BSZ = BN * KP2;
    extern __shared__ float sm[];
    float* Abuf = sm;                       // 3 stages of [MR][36]
    float* Bbuf = sm + 3 * ASZ;             // 3 stages of [BN][36]

    const int tid  = threadIdx.x;
    const int warp = tid >> 5, lane = tid & 31;
    const int g    = lane >> 2, tg = lane & 3;
    const int wm   = (BN == 128) ? (warp >> 1) : ((MR == 128) ? warp : (warp & 3));
    const int wn   = (BN == 128) ? (warp & 1)  : ((MR == 128) ? 0 : (warp >> 2));
    const int mBase = blockIdx.y * MR;
    const int nBase = blockIdx.x * BN;

    const unsigned int smA = (unsigned int)__cvta_generic_to_shared(Abuf);
    const unsigned int smB = (unsigned int)__cvta_generic_to_shared(Bbuf);

    float acc[MT][NTC][4];
    #pragma unroll
    for (int mt = 0; mt < MT; mt++)
        #pragma unroll
        for (int nt = 0; nt < NTC; nt++)
            #pragma unroll
            for (int e = 0; e < 4; e++) acc[mt][nt][e] = 0.f;

    const int nT = K >> 5;
    const int ldRow = tid >> 3, ldCh = (tid & 7) << 2;   // 32 rows per pass

    auto load_stage = [&](int t, int st) {
        const int ks = t << 5;
        float* As = Abuf + st * ASZ;
        float* Bs = Bbuf + st * BSZ;
        #pragma unroll
        for (int i = 0; i < MR / 32; i++) {
            const int row = ldRow + 32 * i;
            cpasync16(&As[row * KP2 + ldCh],
                      A + (size_t)(mBase + row) * K + ks + ldCh);
        }
        #pragma unroll
        for (int i = 0; i < BN / 32; i++) {
            const int row = ldRow + 32 * i;
            cpasync16(&Bs[row * KP2 + ldCh],
                      Bt + (size_t)(nBase + row) * K + ks + ldCh);
        }
        CP_COMMIT();
    };

    load_stage(0, 0);
    load_stage(1, 1);

    const int aRowOff = (lane & 15);
    const int aColOff = (lane >> 4) << 2;
    const int bRowOff = ((lane >> 4) << 3) + (lane & 7);
    const int bColOff = ((lane >> 3) & 1) << 2;

    int st = 0;
    for (int t = 0; t < nT; t++) {
        if (t == nT - 1) { CP_WAIT(0); } else { CP_WAIT(1); }
        __syncthreads();
        if (t + 2 < nT) {
            int st2 = st + 2; if (st2 >= 3) st2 -= 3;
            load_stage(t + 2, st2);
        }
        const unsigned int aSt = smA + (st * ASZ) * 4;
        const unsigned int bSt = smB + (st * BSZ) * 4;

        #pragma unroll
        for (int k8 = 0; k8 < 4; k8++) {
            const int kk = k8 << 3;
            unsigned int bf[NTC][2];
            #pragma unroll
            for (int ntp = 0; ntp < NTC / 2; ntp++) {
                const int n0 = wn * (NTC * 8) + ntp * 16;
                const unsigned int baddr = bSt +
                    (((n0 + bRowOff) * KP2 + kk + bColOff) << 2);
                ldsm_x4(bf[2 * ntp][0], bf[2 * ntp][1],
                        bf[2 * ntp + 1][0], bf[2 * ntp + 1][1], baddr);
            }
            #pragma unroll
            for (int mt = 0; mt < MT; mt++) {
                const int m = (BN == 128) ? (wm * 32 + mt * 16) : (wm * 16);
                unsigned int a0, a1, a2, a3;
                const unsigned int aaddr = aSt +
                    (((m + aRowOff) * KP2 + kk + aColOff) << 2);
                ldsm_x4(a0, a1, a2, a3, aaddr);
                #pragma unroll
                for (int nt = 0; nt < NTC; nt++)
                    mma_tf32(acc[mt][nt], a0, a1, a2, a3, bf[nt][0], bf[nt][1]);
            }
        }
        if (++st >= 3) st -= 3;
    }

    #pragma unroll
    for (int mt = 0; mt < MT; mt++) {
        const int r0 = mBase + ((BN == 128) ? (wm * 32 + mt * 16) : (wm * 16)) + g;
        const int r1 = r0 + 8;
        #pragma unroll
        for (int nt = 0; nt < NTC; nt++) {
            const int col = nBase + wn * (NTC * 8) + nt * 8 + 2 * tg;
            const float b0 = bias[col], b1 = bias[col + 1];
            float e00 = acc[mt][nt][0] + b0, e01 = acc[mt][nt][1] + b1;
            float e10 = acc[mt][nt][2] + b0, e11 = acc[mt][nt][3] + b1;
            const size_t i0 = (size_t)r0 * ldc + col;
            const size_t i1 = (size_t)r1 * ldc + col;
            if (MODE == 5) {
                *(float2*)&C[i0] = make_float2(e00, e01);
                *(float2*)&C[i1] = make_float2(e10, e11);
            } else if (MODE == 1) {
                const float2 a0v = *(const float2*)&aux1[i0];
                const float2 a1v = *(const float2*)&aux1[i1];
                const float2 m0v = *(const float2*)&aux2[i0];
                const float2 m1v = *(const float2*)&aux2[i1];
                *(float2*)&C[i0] = make_float2(e00 + a0v.x + 0.1f * m0v.x,
                                               e01 + a0v.y + 0.1f * m0v.y);
                *(float2*)&C[i1] = make_float2(e10 + a1v.x + 0.1f * m1v.x,
                                               e11 + a1v.y + 0.1f * m1v.y);
            } else if (MODE == 2) {
                e00 = 0.5f * e00 * (1.f + erff(e00 * 0.7071067811865475f));
                e01 = 0.5f * e01 * (1.f + erff(e01 * 0.7071067811865475f));
                e10 = 0.5f * e10 * (1.f + erff(e10 * 0.7071067811865475f));
                e11 = 0.5f * e11 * (1.f + erff(e11 * 0.7071067811865475f));
                *(float2*)&C[i0] = make_float2(e00, e01);
                *(float2*)&C[i1] = make_float2(e10, e11);
            } else if (MODE == 3) {
                const float2 a0v = *(const float2*)&aux1[i0];
                const float2 a1v = *(const float2*)&aux1[i1];
                *(float2*)&C[i0] = make_float2(e00 + a0v.x, e01 + a0v.y);
                *(float2*)&C[i1] = make_float2(e10 + a1v.x, e11 + a1v.y);
            } else {
                const float2 p0 = *(const float2*)&aux1[i0];
                const float2 p1 = *(const float2*)&aux1[i1];
                const float2 q0 = *(const float2*)&aux2[i0];
                const float2 q1 = *(const float2*)&aux2[i1];
                *(float2*)&C[i0]  = make_float2(p0.x + e00, p0.y + e01);
                *(float2*)&C[i1]  = make_float2(p1.x + e10, p1.y + e11);
                *(float2*)&C2[i0] = make_float2(q0.x + e00, q0.y + e01);
                *(float2*)&C2[i1] = make_float2(q1.x + e10, q1.y + e11);
            }
        }
    }

    // -------- fused gate math (MODE 5, block covering cols 1536..1663) -----
    if (MODE == 5 && nBase == 1536) {
        __syncthreads();     // make this block's global C writes visible
        #pragma unroll
        for (int u = 0; u < 4; u++) {
            const int idx = u * 256 + tid;          // 0..1023 = 128 rows x 8 h
            const int row = mBase + (idx >> 3), h = idx & 7;
            const float* gp = C + (size_t)row * ldc + 1536;
            const float xd = gp[h], xgw = gp[8 + h], xgf = gp[16 + h];
            const float d  = fmaxf(xd, 0.f) + log1pf(expf(-fabsf(xd)));
            const float sw = 1.f / (1.f + expf(-xgw));
            const float sf = 1.f / (1.f + expf(-xgf));
            g_coef[row * NH + h] = d * (sw * sw);
            const float dec = fminf(fmaxf(d * (1.f - sf * sf), 1e-6f), 0.999f);
            g_logd[row * NH + h] = logf(dec);
        }
    }
}

// ------- cumsum of log-decay: two-level serial (64 chunks of 16) -----------
__global__ __launch_bounds__(64) void cumsum_k() {
    __shared__ float csum[64];
    const int bh = blockIdx.x, b = bh >> 3, h = bh & 7;
    const int tid = threadIdx.x;
    const int t0 = tid * 16;

    float v[16];
    float acc = 0.f;
    #pragma unroll
    for (int i = 0; i < 16; i++) {
        acc += g_logd[(b * NT + t0 + i) * NH + h];
        v[i] = acc;
    }
    csum[tid] = acc;
    __syncthreads();
    if (tid == 0) {
        float a = 0.f;
        #pragma unroll
        for (int j = 0; j < 64; j++) {
            const float t = csum[j];
            csum[j] = a;
            a += t;
        }
    }
    __syncthreads();
    const float base = csum[tid];
    #pragma unroll
    for (int i = 0; i < 16; i++) {
        const float e = expf(base + v[i]);   // underflows to 0 like the ref
        g_ecum[bh * NT + t0 + i] = e;
        g_invd[bh * NT + t0 + i] = 1.f / (e + 1e-8f);
    }
}

// 4x4 outer-product accumulate: acc[a][c] += q[a] * p[c] (float4 components)
#define OP16(acc, q, p) do {                                                  \
    acc[0][0] = fmaf((q).x, (p).x, acc[0][0]);                                \
    acc[0][1] = fmaf((q).x, (p).y, acc[0][1]);                                \
    acc[0][2] = fmaf((q).x, (p).z, acc[0][2]);                                \
    acc[0][3] = fmaf((q).x, (p).w, acc[0][3]);                                \
    acc[1][0] = fmaf((q).y, (p).x, acc[1][0]);                                \
    acc[1][1] = fmaf((q).y, (p).y, acc[1][1]);                                \
    acc[1][2] = fmaf((q).y, (p).z, acc[1][2]);                                \
    acc[1][3] = fmaf((q).y, (p).w, acc[1][3]);                                \
    acc[2][0] = fmaf((q).z, (p).x, acc[2][0]);                                \
    acc[2][1] = fmaf((q).z, (p).y, acc[2][1]);                                \
    acc[2][2] = fmaf((q).z, (p).z, acc[2][2]);                                \
    acc[2][3] = fmaf((q).z, (p).w, acc[2][3]);                                \
    acc[3][0] = fmaf((q).w, (p).x, acc[3][0]);                                \
    acc[3][1] = fmaf((q).w, (p).y, acc[3][1]);                                \
    acc[3][2] = fmaf((q).w, (p).z, acc[3][2]);                                \
    acc[3][3] = fmaf((q).w, (p).w, acc[3][3]);                                \
} while (0)

// ===== chunked scan phase 1: 3 smem buffers, in-place register transposes ==
#define SP 68
__global__ __launch_bounds__(256, 3) void scan_p1() {
    extern __shared__ float sm[];
    float* sK = sm;                  // [t][j]  -> [j][s] (Kt) -> [s][t] (Gt)
    float* sQ = sm + 64 * SP;        // [t][j]  -> [j][t] (Qt)
    float* sA = sm + 2 * 64 * SP;    // [s][i]
    float* es = sm + 3 * 64 * SP;    // [64]
    const int tc = blockIdx.x, bh = blockIdx.y, b = bh >> 3, h = bh & 7;
    const int tid = threadIdx.x;

    #pragma unroll
    for (int f = 0; f < 4; f++) {
        const int e4 = f * 256 + tid;
        const int tt = e4 >> 4, j4 = (e4 & 15) << 2;
        const int row = b * NT + tc * 64 + tt;
        const float* rp = g_kqv + (size_t)row * LDW + h * 64;
        *(float4*)&sK[tt * SP + j4] = *(const float4*)(rp + j4);
        *(float4*)&sQ[tt * SP + j4] = *(const float4*)(rp + 512 + j4);
        const float4 v = *(const float4*)(rp + 1024 + j4);
        const float sc = g_coef[row * NH + h] * g_invd[bh * NT + tc * 64 + tt];
        float4 a4;
        a4.x = tanhf(v.x) * sc; a4.y = tanhf(v.y) * sc;
        a4.z = tanhf(v.z) * sc; a4.w = tanhf(v.w) * sc;
        *(float4*)&sA[tt * SP + j4] = a4;
    }
    if (tid < 64) es[tid] = g_ecum[bh * NT + tc * 64 + tid];
    __syncthreads();

    {
        const int nr = tid >> 2, nq = tid & 3;
        float sk = 0.f, sq = 0.f;
        #pragma unroll
        for (int e = 0; e < 16; e++) {
            const float kv = sK[nr * SP + nq * 16 + e];
            const float qv = sQ[nr * SP + nq * 16 + e];
            sk = fmaf(kv, kv, sk);
            sq = fmaf(qv, qv, sq);
        }
        sk += __shfl_xor_sync(~0u, sk, 1); sk += __shfl_xor_sync(~0u, sk, 2);
        sq += __shfl_xor_sync(~0u, sq, 1); sq += __shfl_xor_sync(~0u, sq, 2);
        const float ik = 1.f / fmaxf(sqrtf(sk), 1e-12f);
        const float iq = 1.f / fmaxf(sqrtf(sq), 1e-12f);
        #pragma unroll
        for (int e = 0; e < 16; e++) {
            sK[nr * SP + nq * 16 + e] *= ik;
            sQ[nr * SP + nq * 16 + e] *= iq;
        }
    }
    __syncthreads();

    // S_c[i][j] = sum_s A[s][i] * K[s][j]
    {
        const int i4 = (tid & 15) * 4, j4 = (tid >> 4) * 4;
        float acc[4][4];
        #pragma unroll
        for (int a = 0; a < 4; a++)
            #pragma unroll
            for (int c = 0; c < 4; c++) acc[a][c] = 0.f;
        for (int s = 0; s < 64; s++) {
            const float4 av = *(const float4*)&sA[s * SP + i4];
            const float4 kv = *(const float4*)&sK[s * SP + j4];
            OP16(acc, av, kv);
        }
        float* Sp = g_S + ((size_t)bh * NC + tc) * 4096;
        #pragma unroll
        for (int a = 0; a < 4; a++)
            #pragma unroll
            for (int c = 0; c < 4; c++) Sp[(i4 + a) * 64 + j4 + c] = acc[a][c];
    }

    // in-place transpose Q then K
    float4 qr[4];
    {
        #pragma unroll
        for (int f = 0; f < 4; f++) {
            const int e4 = f * 256 + tid;
            const int tt = e4 >> 4, j4 = (e4 & 15) << 2;
            qr[f] = *(const float4*)&sQ[tt * SP + j4];
        }
    }
    __syncthreads();
    {
        float4 kr[4];
        #pragma unroll
        for (int f = 0; f < 4; f++) {
            const int e4 = f * 256 + tid;
            const int tt = e4 >> 4, j4 = (e4 & 15) << 2;
            sQ[(j4 + 0) * SP + tt] = qr[f].x;
            sQ[(j4 + 1) * SP + tt] = qr[f].y;
            sQ[(j4 + 2) * SP + tt] = qr[f].z;
            sQ[(j4 + 3) * SP + tt] = qr[f].w;
            kr[f] = *(const float4*)&sK[tt * SP + j4];
        }
        __syncthreads();
        #pragma unroll
        for (int f = 0; f < 4; f++) {
            const int e4 = f * 256 + tid;
            const int tt = e4 >> 4, j4 = (e4 & 15) << 2;
            sK[(j4 + 0) * SP + tt] = kr[f].x;
            sK[(j4 + 1) * SP + tt] = kr[f].y;
            sK[(j4 + 2) * SP + tt] = kr[f].z;
            sK[(j4 + 3) * SP + tt] = kr[f].w;
        }
    }
    __syncthreads();

    // export normalized Q transposed [j][t] for phase 3
    #pragma unroll
    for (int f = 0; f < 4; f++) {
        const int e4 = f * 256 + tid;
        const int jj = e4 >> 4, t4 = (e4 & 15) << 2;
        *(float4*)&g_qn[(((size_t)bh * NC + tc) * 64 + jj) * 64 + t4] =
            *(const float4*)&sQ[jj * SP + t4];
    }

    // G[t][s] (causal) from Qt/Kt; overwrite sK with Gt[s][t]
    {
        const int t4 = (tid & 15) * 4, s4 = (tid >> 4) * 4;
        float acc[4][4];
        #pragma unroll
        for (int a = 0; a < 4; a++)
            #pragma unroll
            for (int c = 0; c < 4; c++) acc[a][c] = 0.f;
        if (s4 <= t4 + 3) {
            for (int j = 0; j < 64; j++) {
                const float4 qv = *(const float4*)&sQ[j * SP + t4];
                const float4 kv = *(const float4*)&sK[j * SP + s4];
                OP16(acc, qv, kv);
            }
        }
        __syncthreads();
        #pragma unroll
        for (int c = 0; c < 4; c++) {
            float4 o;
            o.x = (s4 + c <= t4 + 0) ? acc[0][c] : 0.f;
            o.y = (s4 + c <= t4 + 1) ? acc[1][c] : 0.f;
            o.z = (s4 + c <= t4 + 2) ? acc[2][c] : 0.f;
            o.w = (s4 + c <= t4 + 3) ? acc[3][c] : 0.f;
            *(float4*)&sK[(s4 + c) * SP + t4] = o;
        }
    }
    __syncthreads();

    // r_local[t][i] = sum_{s<=t} G[t][s] * A[s][i]; store es_t * r_local
    {
        const int t4 = (tid & 15) * 4, i4 = (tid >> 4) * 4;
        float acc[4][4];
        #pragma unroll
        for (int a = 0; a < 4; a++)
            #pragma unroll
            for (int c = 0; c < 4; c++) acc[a][c] = 0.f;
        const int smax = t4 + 4;
        for (int s = 0; s < smax; s++) {
            const float4 gv = *(const float4*)&sK[s * SP + t4];
            const float4 av = *(const float4*)&sA[s * SP + i4];
            OP16(acc, gv, av);
        }
        #pragma unroll
        for (int a = 0; a < 4; a++) {
            const float e = es[t4 + a];
            const size_t ro = (size_t)(b * NT + tc * 64 + t4 + a) * NHD + h * 64;
            #pragma unroll
            for (int c = 0; c < 4; c++) g_read[ro + i4 + c] = e * acc[a][c];
        }
    }
}

// ============ phase 2: exclusive prefix of chunk sums + next_mem ===========
__global__ __launch_bounds__(256) void scan_p2(float* __restrict__ next_mem) {
    const int bh = blockIdx.x;
    const int e  = blockIdx.y * 256 + threadIdx.x;      // 0..4095
    const float elast = g_ecum[bh * NT + NT - 1];
    float acc = 0.f;
    #pragma unroll
    for (int c = 0; c < NC; c++) {
        g_P[((size_t)bh * NC + c) * 4096 + e] = acc;
        acc += g_S[((size_t)bh * NC + c) * 4096 + e];
    }
    next_mem[(size_t)bh * 4096 + e] = acc * elast;
}

// ============ phase 3: cross term r += es_t * (P_{c-1} q_t) ================
__global__ __launch_bounds__(256) void scan_p3() {
    __shared__ float sQt[64 * SP];
    __shared__ float sPt[64 * SP];
    __shared__ float es[64];
    const int tc = blockIdx.x + 1, bh = blockIdx.y, b = bh >> 3, h = bh & 7;
    const int tid = threadIdx.x;
    #pragma unroll
    for (int f = 0; f < 4; f++) {
        const int e4 = f * 256 + tid;
        const int r = e4 >> 4, c4 = (e4 & 15) << 2;
        *(float4*)&sQt[r * SP + c4] =
            *(const float4*)&g_qn[(((size_t)bh * NC + tc) * 64 + r) * 64 + c4];
        const float4 p =
            *(const float4*)&g_P[((size_t)bh * NC + tc) * 4096 + r * 64 + c4];
        sPt[(c4 + 0) * SP + r] = p.x; sPt[(c4 + 1) * SP + r] = p.y;
        sPt[(c4 + 2) * SP + r] = p.z; sPt[(c4 + 3) * SP + r] = p.w;
    }
    if (tid < 64) es[tid] = g_ecum[bh * NT + tc * 64 + tid];
    __syncthreads();

    const int t4 = (tid & 15) * 4, i4 = (tid >> 4) * 4;
    float acc[4][4];
    #pragma unroll
    for (int a = 0; a < 4; a++)
        #pragma unroll
        for (int c = 0; c < 4; c++) acc[a][c] = 0.f;
    for (int j = 0; j < 64; j++) {
        const float4 qv = *(const float4*)&sQt[j * SP + t4];
        const float4 pv = *(const float4*)&sPt[j * SP + i4];
        OP16(acc, qv, pv);
    }
    #pragma unroll
    for (int a = 0; a < 4; a++) {
        const float e = es[t4 + a];
        const size_t ro = (size_t)(b * NT + tc * 64 + t4 + a) * NHD + h * 64;
        #pragma unroll
        for (int c = 0; c < 4; c++) g_read[ro + i4 + c] += e * acc[a][c];
    }
}

// ---------------------------------------------------------------- launch ---
static float* sym(const void* s) {
    void* p = nullptr;
    cudaGetSymbolAddress(&p, s);
    return (float*)p;
}

extern "C" void kernel_launch(void* const* d_in, const int* in_sizes, int n_in,
                              void* d_out, int out_size) {
    const float* x     = (const float*)d_in[0];
    const float* b_min = (const float*)d_in[1];
    const float* b_max = (const float*)d_in[2];
    const float* motif = (const float*)d_in[3];
    const float* Wk    = (const float*)d_in[4];
    const float* bk    = (const float*)d_in[5];
    const float* Wq    = (const float*)d_in[6];
    const float* bq    = (const float*)d_in[7];
    const float* Wv    = (const float*)d_in[8];
    const float* bv    = (const float*)d_in[9];
    const float* Wo    = (const float*)d_in[10];
    const float* bo    = (const float*)d_in[11];
    const float* Wd    = (const float*)d_in[12];
    const float* bd    = (const float*)d_in[13];
    const float* Wgw   = (const float*)d_in[14];
    const float* bgw   = (const float*)d_in[15];
    const float* Wgf   = (const float*)d_in[16];
    const float* bgf   = (const float*)d_in[17];
    const float* Wps   = (const float*)d_in[18];
    const float* bps   = (const float*)d_in[19];
    const float* ln1g  = (const float*)d_in[20];
    const float* ln1b  = (const float*)d_in[21];
    const float* ln2g  = (const float*)d_in[22];
    const float* ln2b  = (const float*)d_in[23];
    const float* W1    = (const float*)d_in[24];
    const float* b1    = (const float*)d_in[25];
    const float* W2    = (const float*)d_in[26];
    const float* b2    = (const float*)d_in[27];

    float* out    = (float*)d_out;
    float* out_x3 = out;                            // [2,1024,512]
    float* out_nm = out + (size_t)NROWS * NE;       // [2,8,64,64]
    float* out_pm = out_nm + NBH * ND * ND;         // b_min + probe
    float* out_px = out_pm + (size_t)NROWS * NE;    // b_max + probe

    float* xn   = sym(g_xn);
    float* WT1  = sym(g_WT1);
    float* WoT  = sym(g_WoT);
    float* W1T  = sym(g_W1T);
    float* W2T  = sym(g_W2T);
    float* WpsT = sym(g_WpsT);
    float* bkqv = sym(g_bkqv);
    float* kqv  = sym(g_kqv);
    float* rd   = sym(g_read);
    float* x2   = sym(g_x2);
    float* hh   = sym(g_hh);
    float* mid  = sym(g_mid);

    const int SM128 = 3 * (128 * KP2 + 128 * KP2) * 4;   // 110592
    const int SM64  = 3 * (64 * KP2 + 64 * KP2)   * 4;   // 55296
    const int SMP1  = (3 * 64 * SP + 64) * 4;            // 52480
    cudaFuncSetAttribute(tgemm_k<5,128,128>, cudaFuncAttributeMaxDynamicSharedMemorySize, SM128);
    cudaFuncSetAttribute(tgemm_k<2,128,128>, cudaFuncAttributeMaxDynamicSharedMemorySize, SM128);
    cudaFuncSetAttribute(tgemm_k<1,64,64>,   cudaFuncAttributeMaxDynamicSharedMemorySize, SM64);
    cudaFuncSetAttribute(tgemm_k<3,64,64>,   cudaFuncAttributeMaxDynamicSharedMemorySize, SM64);
    cudaFuncSetAttribute(tgemm_k<4,64,64>,   cudaFuncAttributeMaxDynamicSharedMemorySize, SM64);
    cudaFuncSetAttribute(scan_p1,            cudaFuncAttributeMaxDynamicSharedMemorySize, SMP1);

    // fused: LN1 + all weight transposes + bias/zero packing
    const int ZB_BLOCKS = (104 * NE + 255) / 256;        // 208
    ln_prep_k<<<NROWS + TRANS_BLOCKS + ZB_BLOCKS, 256>>>(
        x, ln1g, ln1b, Wk, Wq, Wv, Wd, Wgw, Wgf, Wo, W1, W2, Wps,
        bk, bq, bv, bd, bgw, bgf);                                             // 0
    tgemm_k<5,128,128><<<dim3(13, 16), 256, SM128>>>(xn, WT1, bkqv, kqv,
                                                     512, LDW,
                                                     nullptr, nullptr, nullptr);// 1
    cumsum_k<<<NBH, 64>>>();                                                   // 2
    scan_p1<<<dim3(NC, NBH), 256, SMP1>>>();                                   // 3
    scan_p2<<<dim3(NBH, 16), 256>>>(out_nm);                                   // 4
    scan_p3<<<dim3(NC - 1, NBH), 256>>>();                                     // 5

    tgemm_k<1,64,64><<<dim3(8, 32), 256, SM64>>>(rd, WoT, bo, x2, 512, 512,
                                                 x, motif, nullptr);           // 6
    ln_k<<<NROWS, 256>>>(x2, ln2g, ln2b, hh);                                  // 7
    tgemm_k<2,128,128><<<dim3(16, 16), 256, SM128>>>(hh, W1T, b1, mid,
                                                     512, 2048,
                                                     nullptr, nullptr, nullptr);// 8
    tgemm_k<3,64,64><<<dim3(8, 32), 256, SM64>>>(mid, W2T, b2, out_x3,
                                                 2048, 512,
                                                 x2, nullptr, nullptr);        // 9
    tgemm_k<4,64,64><<<dim3(8, 32), 256, SM64>>>(out_x3, WpsT, bps, out_pm,
                                                 512, 512,
                                                 b_min, b_max, out_px);        // 10
}

// round 15
// speedup vs baseline: 1.1029x; 1.0204x over previous
#include <cuda_runtime.h>
#include <math.h>

#define NE    512
#define NH    8
#define ND    64
#define NB    2
#define NT    1024
#define NHD   512
#define NROWS 2048          // B*T
#define NFFN  2048
#define NBH   16
#define NC    16            // chunks of 64 along T
#define LDW   1664          // packed fused-proj width (1536 kqv + 24 gates + pad)

// ------------------------------ scratch (static device globals; no allocs) --
static __device__ float g_xn  [NROWS * NE];          // LN1 output
static __device__ float g_WT1 [LDW * NE];            // fused W^T [n][k]
static __device__ float g_WoT [NE * NHD];            // Wo^T  [n][k]
static __device__ float g_W1T [NFFN * NE];           // W1^T
static __device__ float g_W2T [NE * NFFN];           // W2^T
static __device__ float g_WpsT[NE * NE];             // Wps^T
static __device__ float g_bkqv[LDW];
static __device__ float g_kqv [NROWS * LDW];         // raw k|q|v|gates
static __device__ float g_coef[NROWS * NH];          // d*gw
static __device__ float g_logd[NROWS * NH];          // log(clip(d*gf))
static __device__ float g_ecum[NBH * NT];            // exp(cumsum(log decay))
static __device__ float g_invd[NBH * NT];            // 1/(ecum+1e-8)
static __device__ float g_read[NROWS * NHD];         // readout
static __device__ float g_x2  [NROWS * NE];
static __device__ float g_hh  [NROWS * NE];          // LN2 output
static __device__ float g_mid [NROWS * NFFN];        // gelu(h@W1+b1)
static __device__ float g_qn  [NBH * NC * 64 * 64];  // normalized q [j][t]
static __device__ float g_S   [NBH * NC * 64 * 64];  // per-chunk state sums
static __device__ float g_P   [NBH * NC * 64 * 64];  // exclusive prefixes

// ----------------------- generic 32x32 tiled transpose body ----------------
__device__ __forceinline__ void trans_body(const float* __restrict__ src,
                                           float* __restrict__ dst,
                                           int K, int N, int dro, int t,
                                           int tid, float* tile /*32*33*/) {
    const int ntx = (N + 31) >> 5;
    const int nb = (t % ntx) * 32, kb = (t / ntx) * 32;
    const int tx = tid & 31, ty = tid >> 5;
    #pragma unroll
    for (int i = 0; i < 4; i++) {
        const int k = kb + ty + i * 8, n = nb + tx;
        if (n < N) tile[(ty + i * 8) * 33 + tx] = src[(size_t)k * N + n];
    }
    __syncthreads();
    #pragma unroll
    for (int i = 0; i < 4; i++) {
        const int n = nb + ty + i * 8, k = kb + tx;
        if (n < N) dst[(size_t)(dro + n) * K + k] = tile[tx * 33 + ty + i * 8];
    }
}

// ------------------- single-pass LayerNorm (sum + sumsq together) ----------
__device__ __forceinline__ void ln_body(const float* __restrict__ x,
                                        const float* __restrict__ g,
                                        const float* __restrict__ b,
                                        float* __restrict__ o,
                                        int row, int tid, float* sh) {
    const float v0 = x[(size_t)row * NE + tid];
    const float v1 = x[(size_t)row * NE + tid + 256];

    float s  = v0 + v1;
    float s2 = v0 * v0 + v1 * v1;
    #pragma unroll
    for (int off = 16; off; off >>= 1) {
        s  += __shfl_xor_sync(~0u, s,  off);
        s2 += __shfl_xor_sync(~0u, s2, off);
    }
    if ((tid & 31) == 0) { sh[tid >> 5] = s; sh[8 + (tid >> 5)] = s2; }
    __syncthreads();
    if (tid < 32) {
        float t  = (tid < 8) ? sh[tid] : 0.f;
        float t2 = (tid < 8) ? sh[8 + tid] : 0.f;
        #pragma unroll
        for (int off = 4; off; off >>= 1) {
            t  += __shfl_xor_sync(~0u, t,  off);
            t2 += __shfl_xor_sync(~0u, t2, off);
        }
        if (tid == 0) { sh[0] = t; sh[8] = t2; }
    }
    __syncthreads();
    const float mu  = sh[0] * (1.f / NE);
    const float var = sh[8] * (1.f / NE) - mu * mu;
    const float inv = 1.f / sqrtf(var + 1e-5f);

    o[(size_t)row * NE + tid]       = (v0 - mu) * inv * g[tid]       + b[tid];
    o[(size_t)row * NE + tid + 256] = (v1 - mu) * inv * g[tid + 256] + b[tid + 256];
}

__global__ __launch_bounds__(256) void ln_k(const float* __restrict__ x,
                                            const float* __restrict__ g,
                                            const float* __restrict__ b,
                                            float* __restrict__ o) {
    __shared__ float sh[16];
    ln_body(x, g, b, o, blockIdx.x, threadIdx.x, sh);
}

// --- fused: LN1 (0..2047) + WT1 transposes (816) + bias/zero (208) --------
#define WT1_BLOCKS 816
__global__ __launch_bounds__(256) void ln_prep_k(
    const float* __restrict__ x, const float* __restrict__ ln1g,
    const float* __restrict__ ln1b,
    const float* __restrict__ Wk, const float* __restrict__ Wq,
    const float* __restrict__ Wv, const float* __restrict__ Wd,
    const float* __restrict__ Wgw, const float* __restrict__ Wgf,
    const float* __restrict__ bk, const float* __restrict__ bq,
    const float* __restrict__ bv, const float* __restrict__ bd,
    const float* __restrict__ bgw, const float* __restrict__ bgf) {
    __shared__ float sh[16];
    __shared__ float tile[32 * 33];
    if (blockIdx.x < NROWS) {
        ln_body(x, ln1g, ln1b, g_xn, blockIdx.x, threadIdx.x, sh);
        return;
    }
    if (blockIdx.x < NROWS + WT1_BLOCKS) {
        const int bid = blockIdx.x - NROWS;
        const float* src; int N, dro, t;
        if      (bid < 256) { src = Wk;  N = 512; dro = 0;    t = bid; }
        else if (bid < 512) { src = Wq;  N = 512; dro = 512;  t = bid - 256; }
        else if (bid < 768) { src = Wv;  N = 512; dro = 1024; t = bid - 512; }
        else if (bid < 784) { src = Wd;  N = 8;   dro = 1536; t = bid - 768; }
        else if (bid < 800) { src = Wgw; N = 8;   dro = 1544; t = bid - 784; }
        else                { src = Wgf; N = 8;   dro = 1552; t = bid - 800; }
        trans_body(src, g_WT1, 512, N, dro, t, threadIdx.x, tile);
        return;
    }
    // zero pad rows 1560..1663 of WT1 + pack biases
    const int idx = (blockIdx.x - NROWS - WT1_BLOCKS) * 256 + threadIdx.x;
    if (idx < 104 * NE) g_WT1[(size_t)1560 * NE + idx] = 0.f;
    if (idx < LDW) {
        float bb;
        if (idx < 512)        bb = bk[idx];
        else if (idx < 1024)  bb = bq[idx - 512];
        else if (idx < 1536)  bb = bv[idx - 1024];
        else if (idx < 1544)  bb = bd [idx - 1536];
        else if (idx < 1552)  bb = bgw[idx - 1544];
        else if (idx < 1560)  bb = bgf[idx - 1552];
        else                  bb = 0.f;
        g_bkqv[idx] = bb;
    }
}

// -------------------------------------------- mma + cp.async + ldmatrix ----
__device__ __forceinline__ void mma_tf32(float* d,
                                         unsigned int a0, unsigned int a1,
                                         unsigned int a2, unsigned int a3,
                                         unsigned int b0, unsigned int b1) {
    asm volatile(
        "mma.sync.aligned.m16n8k8.row.col.f32.tf32.tf32.f32 "
        "{%0,%1,%2,%3}, {%4,%5,%6,%7}, {%8,%9}, {%0,%1,%2,%3};"
        : "+f"(d[0]), "+f"(d[1]), "+f"(d[2]), "+f"(d[3])
        : "r"(a0), "r"(a1), "r"(a2), "r"(a3), "r"(b0), "r"(b1));
}

__device__ __forceinline__ void ldsm_x4(unsigned int& r0, unsigned int& r1,
                                        unsigned int& r2, unsigned int& r3,
                                        unsigned int addr) {
    asm volatile("ldmatrix.sync.aligned.m8n8.x4.shared.b16 {%0,%1,%2,%3}, [%4];"
                 : "=r"(r0), "=r"(r1), "=r"(r2), "=r"(r3) : "r"(addr));
}

__device__ __forceinline__ void cpasync16(void* s, const void* g) {
    unsigned int sa = (unsigned int)__cvta_generic_to_shared(s);
    asm volatile("cp.async.cg.shared.global [%0], [%1], 16;" :: "r"(sa), "l"(g));
}
#define CP_COMMIT()  asm volatile("cp.async.commit_group;")
#define CP_WAIT(n)   asm volatile("cp.async.wait_group %0;" :: "n"(n))

// --- tf32 tensor GEMM: C[MR,BN] tiles = A[M,K] @ Bt[N,K]^T -----------------
// MODE 1: C = v + aux1 + 0.1*aux2   MODE 2: C = gelu(v)
// MODE 3: C = v + aux1              MODE 4: C = aux1+v; C2 = aux2+v
// MODE 5: C = v, plus fused gate math on tile covering cols 1536..1663
#define KP2 36
template <int MODE, int BN, int MR>
__global__ __launch_bounds__(256, 2) void tgemm_k(
    const float* __restrict__ A, const float* __restrict__ Bt,
    const float* __restrict__ bias, float* __restrict__ C,
    int K, int ldc,
    const float* __restrict__ aux1, const float* __restrict__ aux2,
    float* __restrict__ C2) {
    constexpr int MT  = (BN == 128) ? 2 : 1;
    constexpr int NTC = (BN == 128) ? 8 : ((MR == 128) ? 8 : 4);
    constexpr int ASZ = MR * KP2;
    constexpr int BSZ = BN * KP2;
    extern __shared__ float sm[];
    float* Abuf = sm;                       // 3 stages of [MR][36]
    float* Bbuf = sm + 3 * ASZ;             // 3 stages of [BN][36]

    const int tid  = threadIdx.x;
    const int warp = tid >> 5, lane = tid & 31;
    const int g    = lane >> 2, tg = lane & 3;
    const int wm   = (BN == 128) ? (warp >> 1) : ((MR == 128) ? warp : (warp & 3));
    const int wn   = (BN == 128) ? (warp & 1)  : ((MR == 128) ? 0 : (warp >> 2));
    const int mBase = blockIdx.y * MR;
    const int nBase = blockIdx.x * BN;

    const unsigned int smA = (unsigned int)__cvta_generic_to_shared(Abuf);
    const unsigned int smB = (unsigned int)__cvta_generic_to_shared(Bbuf);

    float acc[MT][NTC][4];
    #pragma unroll
    for (int mt = 0; mt < MT; mt++)
        #pragma unroll
        for (int nt = 0; nt < NTC; nt++)
            #pragma unroll
            for (int e = 0; e < 4; e++) acc[mt][nt][e] = 0.f;

    const int nT = K >> 5;
    const int ldRow = tid >> 3, ldCh = (tid & 7) << 2;   // 32 rows per pass

    auto load_stage = [&](int t, int st) {
        const int ks = t << 5;
        float* As = Abuf + st * ASZ;
        float* Bs = Bbuf + st * BSZ;
        #pragma unroll
        for (int i = 0; i < MR / 32; i++) {
            const int row = ldRow + 32 * i;
            cpasync16(&As[row * KP2 + ldCh],
                      A + (size_t)(mBase + row) * K + ks + ldCh);
        }
        #pragma unroll
        for (int i = 0; i < BN / 32; i++) {
            const int row = ldRow + 32 * i;
            cpasync16(&Bs[row * KP2 + ldCh],
                      Bt + (size_t)(nBase + row) * K + ks + ldCh);
        }
        CP_COMMIT();
    };

    load_stage(0, 0);
    load_stage(1, 1);

    const int aRowOff = (lane & 15);
    const int aColOff = (lane >> 4) << 2;
    const int bRowOff = ((lane >> 4) << 3) + (lane & 7);
    const int bColOff = ((lane >> 3) & 1) << 2;

    int st = 0;
    for (int t = 0; t < nT; t++) {
        if (t == nT - 1) { CP_WAIT(0); } else { CP_WAIT(1); }
        __syncthreads();
        if (t + 2 < nT) {
            int st2 = st + 2; if (st2 >= 3) st2 -= 3;
            load_stage(t + 2, st2);
        }
        const unsigned int aSt = smA + (st * ASZ) * 4;
        const unsigned int bSt = smB + (st * BSZ) * 4;

        #pragma unroll
        for (int k8 = 0; k8 < 4; k8++) {
            const int kk = k8 << 3;
            unsigned int bf[NTC][2];
            #pragma unroll
            for (int ntp = 0; ntp < NTC / 2; ntp++) {
                const int n0 = wn * (NTC * 8) + ntp * 16;
                const unsigned int baddr = bSt +
                    (((n0 + bRowOff) * KP2 + kk + bColOff) << 2);
                ldsm_x4(bf[2 * ntp][0], bf[2 * ntp][1],
                        bf[2 * ntp + 1][0], bf[2 * ntp + 1][1], baddr);
            }
            #pragma unroll
            for (int mt = 0; mt < MT; mt++) {
                const int m = (BN == 128) ? (wm * 32 + mt * 16) : (wm * 16);
                unsigned int a0, a1, a2, a3;
                const unsigned int aaddr = aSt +
                    (((m + aRowOff) * KP2 + kk + aColOff) << 2);
                ldsm_x4(a0, a1, a2, a3, aaddr);
                #pragma unroll
                for (int nt = 0; nt < NTC; nt++)
                    mma_tf32(acc[mt][nt], a0, a1, a2, a3, bf[nt][0], bf[nt][1]);
            }
        }
        if (++st >= 3) st -= 3;
    }

    #pragma unroll
    for (int mt = 0; mt < MT; mt++) {
        const int r0 = mBase + ((BN == 128) ? (wm * 32 + mt * 16) : (wm * 16)) + g;
        const int r1 = r0 + 8;
        #pragma unroll
        for (int nt = 0; nt < NTC; nt++) {
            const int col = nBase + wn * (NTC * 8) + nt * 8 + 2 * tg;
            const float b0 = bias[col], b1 = bias[col + 1];
            float e00 = acc[mt][nt][0] + b0, e01 = acc[mt][nt][1] + b1;
            float e10 = acc[mt][nt][2] + b0, e11 = acc[mt][nt][3] + b1;
            const size_t i0 = (size_t)r0 * ldc + col;
            const size_t i1 = (size_t)r1 * ldc + col;
            if (MODE == 5) {
                *(float2*)&C[i0] = make_float2(e00, e01);
                *(float2*)&C[i1] = make_float2(e10, e11);
            } else if (MODE == 1) {
                const float2 a0v = *(const float2*)&aux1[i0];
                const float2 a1v = *(const float2*)&aux1[i1];
                const float2 m0v = *(const float2*)&aux2[i0];
                const float2 m1v = *(const float2*)&aux2[i1];
                *(float2*)&C[i0] = make_float2(e00 + a0v.x + 0.1f * m0v.x,
                                               e01 + a0v.y + 0.1f * m0v.y);
                *(float2*)&C[i1] = make_float2(e10 + a1v.x + 0.1f * m1v.x,
                                               e11 + a1v.y + 0.1f * m1v.y);
            } else if (MODE == 2) {
                e00 = 0.5f * e00 * (1.f + erff(e00 * 0.7071067811865475f));
                e01 = 0.5f * e01 * (1.f + erff(e01 * 0.7071067811865475f));
                e10 = 0.5f * e10 * (1.f + erff(e10 * 0.7071067811865475f));
                e11 = 0.5f * e11 * (1.f + erff(e11 * 0.7071067811865475f));
                *(float2*)&C[i0] = make_float2(e00, e01);
                *(float2*)&C[i1] = make_float2(e10, e11);
            } else if (MODE == 3) {
                const float2 a0v = *(const float2*)&aux1[i0];
                const float2 a1v = *(const float2*)&aux1[i1];
                *(float2*)&C[i0] = make_float2(e00 + a0v.x, e01 + a0v.y);
                *(float2*)&C[i1] = make_float2(e10 + a1v.x, e11 + a1v.y);
            } else {
                const float2 p0 = *(const float2*)&aux1[i0];
                const float2 p1 = *(const float2*)&aux1[i1];
                const float2 q0 = *(const float2*)&aux2[i0];
                const float2 q1 = *(const float2*)&aux2[i1];
                *(float2*)&C[i0]  = make_float2(p0.x + e00, p0.y + e01);
                *(float2*)&C[i1]  = make_float2(p1.x + e10, p1.y + e11);
                *(float2*)&C2[i0] = make_float2(q0.x + e00, q0.y + e01);
                *(float2*)&C2[i1] = make_float2(q1.x + e10, q1.y + e11);
            }
        }
    }

    // -------- fused gate math (MODE 5, block covering cols 1536..1663) -----
    if (MODE == 5 && nBase == 1536) {
        __syncthreads();     // make this block's global C writes visible
        #pragma unroll
        for (int u = 0; u < 4; u++) {
            const int idx = u * 256 + tid;          // 0..1023 = 128 rows x 8 h
            const int row = mBase + (idx >> 3), h = idx & 7;
            const float* gp = C + (size_t)row * ldc + 1536;
            const float xd = gp[h], xgw = gp[8 + h], xgf = gp[16 + h];
            const float d  = fmaxf(xd, 0.f) + log1pf(expf(-fabsf(xd)));
            const float sw = 1.f / (1.f + expf(-xgw));
            const float sf = 1.f / (1.f + expf(-xgf));
            g_coef[row * NH + h] = d * (sw * sw);
            const float dec = fminf(fmaxf(d * (1.f - sf * sf), 1e-6f), 0.999f);
            g_logd[row * NH + h] = logf(dec);
        }
    }
}

// ---- cumsum (blocks 0..15, tid<64 active) + big-weight transposes (rest) --
#define XT_BLOCKS 2560      // Wo(256) | W1(1024) | W2(1024) | Wps(256)
__global__ __launch_bounds__(256) void cumsum_k(
    const float* __restrict__ Wo, const float* __restrict__ W1,
    const float* __restrict__ W2, const float* __restrict__ Wps) {
    __shared__ float csum[64];
    __shared__ float tile[32 * 33];
    if (blockIdx.x >= NBH) {
        const int id = blockIdx.x - NBH;
        const float* src; float* dst; int K, N, t;
        if      (id < 256)  { src = Wo;  dst = g_WoT;  K = 512;  N = 512;  t = id; }
        else if (id < 1280) { src = W1;  dst = g_W1T;  K = 512;  N = 2048; t = id - 256; }
        else if (id < 2304) { src = W2;  dst = g_W2T;  K = 2048; N = 512;  t = id - 1280; }
        else                { src = Wps; dst = g_WpsT; K = 512;  N = 512;  t = id - 2304; }
        trans_body(src, dst, K, N, 0, t, threadIdx.x, tile);
        return;
    }
    const int bh = blockIdx.x, b = bh >> 3, h = bh & 7;
    const int tid = threadIdx.x;

    float v[16];
    if (tid < 64) {
        const int t0 = tid * 16;
        float acc = 0.f;
        #pragma unroll
        for (int i = 0; i < 16; i++) {
            acc += g_logd[(b * NT + t0 + i) * NH + h];
            v[i] = acc;
        }
        csum[tid] = acc;
    }
    __syncthreads();
    if (tid == 0) {
        float a = 0.f;
        #pragma unroll
        for (int j = 0; j < 64; j++) {
            const float t = csum[j];
            csum[j] = a;
            a += t;
        }
    }
    __syncthreads();
    if (tid < 64) {
        const int t0 = tid * 16;
        const float base = csum[tid];
        #pragma unroll
        for (int i = 0; i < 16; i++) {
            const float e = expf(base + v[i]);   // underflows to 0 like the ref
            g_ecum[bh * NT + t0 + i] = e;
            g_invd[bh * NT + t0 + i] = 1.f / (e + 1e-8f);
        }
    }
}

// 4x4 outer-product accumulate: acc[a][c] += q[a] * p[c] (float4 components)
#define OP16(acc, q, p) do {                                                  \
    acc[0][0] = fmaf((q).x, (p).x, acc[0][0]);                                \
    acc[0][1] = fmaf((q).x, (p).y, acc[0][1]);                                \
    acc[0][2] = fmaf((q).x, (p).z, acc[0][2]);                                \
    acc[0][3] = fmaf((q).x, (p).w, acc[0][3]);                                \
    acc[1][0] = fmaf((q).y, (p).x, acc[1][0]);                                \
    acc[1][1] = fmaf((q).y, (p).y, acc[1][1]);                                \
    acc[1][2] = fmaf((q).y, (p).z, acc[1][2]);                                \
    acc[1][3] = fmaf((q).y, (p).w, acc[1][3]);                                \
    acc[2][0] = fmaf((q).z, (p).x, acc[2][0]);                                \
    acc[2][1] = fmaf((q).z, (p).y, acc[2][1]);                                \
    acc[2][2] = fmaf((q).z, (p).z, acc[2][2]);                                \
    acc[2][3] = fmaf((q).z, (p).w, acc[2][3]);                                \
    acc[3][0] = fmaf((q).w, (p).x, acc[3][0]);                                \
    acc[3][1] = fmaf((q).w, (p).y, acc[3][1]);                                \
    acc[3][2] = fmaf((q).w, (p).z, acc[3][2]);                                \
    acc[3][3] = fmaf((q).w, (p).w, acc[3][3]);                                \
} while (0)

// ===== chunked scan phase 1: 3 smem buffers, in-place register transposes ==
#define SP 68
__global__ __launch_bounds__(256, 3) void scan_p1() {
    extern __shared__ float sm[];
    float* sK = sm;                  // [t][j]  -> [j][s] (Kt) -> [s][t] (Gt)
    float* sQ = sm + 64 * SP;        // [t][j]  -> [j][t] (Qt)
    float* sA = sm + 2 * 64 * SP;    // [s][i]
    float* es = sm + 3 * 64 * SP;    // [64]
    const int tc = blockIdx.x, bh = blockIdx.y, b = bh >> 3, h = bh & 7;
    const int tid = threadIdx.x;

    #pragma unroll
    for (int f = 0; f < 4; f++) {
        const int e4 = f * 256 + tid;
        const int tt = e4 >> 4, j4 = (e4 & 15) << 2;
        const int row = b * NT + tc * 64 + tt;
        const float* rp = g_kqv + (size_t)row * LDW + h * 64;
        *(float4*)&sK[tt * SP + j4] = *(const float4*)(rp + j4);
        *(float4*)&sQ[tt * SP + j4] = *(const float4*)(rp + 512 + j4);
        const float4 v = *(const float4*)(rp + 1024 + j4);
        const float sc = g_coef[row * NH + h] * g_invd[bh * NT + tc * 64 + tt];
        float4 a4;
        a4.x = tanhf(v.x) * sc; a4.y = tanhf(v.y) * sc;
        a4.z = tanhf(v.z) * sc; a4.w = tanhf(v.w) * sc;
        *(float4*)&sA[tt * SP + j4] = a4;
    }
    if (tid < 64) es[tid] = g_ecum[bh * NT + tc * 64 + tid];
    __syncthreads();

    {
        const int nr = tid >> 2, nq = tid & 3;
        float sk = 0.f, sq = 0.f;
        #pragma unroll
        for (int e = 0; e < 16; e++) {
            const float kv = sK[nr * SP + nq * 16 + e];
            const float qv = sQ[nr * SP + nq * 16 + e];
            sk = fmaf(kv, kv, sk);
            sq = fmaf(qv, qv, sq);
        }
        sk += __shfl_xor_sync(~0u, sk, 1); sk += __shfl_xor_sync(~0u, sk, 2);
        sq += __shfl_xor_sync(~0u, sq, 1); sq += __shfl_xor_sync(~0u, sq, 2);
        const float ik = 1.f / fmaxf(sqrtf(sk), 1e-12f);
        const float iq = 1.f / fmaxf(sqrtf(sq), 1e-12f);
        #pragma unroll
        for (int e = 0; e < 16; e++) {
            sK[nr * SP + nq * 16 + e] *= ik;
            sQ[nr * SP + nq * 16 + e] *= iq;
        }
    }
    __syncthreads();

    // S_c[i][j] = sum_s A[s][i] * K[s][j]
    {
        const int i4 = (tid & 15) * 4, j4 = (tid >> 4) * 4;
        float acc[4][4];
        #pragma unroll
        for (int a = 0; a < 4; a++)
            #pragma unroll
            for (int c = 0; c < 4; c++) acc[a][c] = 0.f;
        for (int s = 0; s < 64; s++) {
            const float4 av = *(const float4*)&sA[s * SP + i4];
            const float4 kv = *(const float4*)&sK[s * SP + j4];
            OP16(acc, av, kv);
        }
        float* Sp = g_S + ((size_t)bh * NC + tc) * 4096;
        #pragma unroll
        for (int a = 0; a < 4; a++)
            #pragma unroll
            for (int c = 0; c < 4; c++) Sp[(i4 + a) * 64 + j4 + c] = acc[a][c];
    }

    // in-place transpose Q then K
    float4 qr[4];
    {
        #pragma unroll
        for (int f = 0; f < 4; f++) {
            const int e4 = f * 256 + tid;
            const int tt = e4 >> 4, j4 = (e4 & 15) << 2;
            qr[f] = *(const float4*)&sQ[tt * SP + j4];
        }
    }
    __syncthreads();
    {
        float4 kr[4];
        #pragma unroll
        for (int f = 0; f < 4; f++) {
            const int e4 = f * 256 + tid;
            const int tt = e4 >> 4, j4 = (e4 & 15) << 2;
            sQ[(j4 + 0) * SP + tt] = qr[f].x;
            sQ[(j4 + 1) * SP + tt] = qr[f].y;
            sQ[(j4 + 2) * SP + tt] = qr[f].z;
            sQ[(j4 + 3) * SP + tt] = qr[f].w;
            kr[f] = *(const float4*)&sK[tt * SP + j4];
        }
        __syncthreads();
        #pragma unroll
        for (int f = 0; f < 4; f++) {
            const int e4 = f * 256 + tid;
            const int tt = e4 >> 4, j4 = (e4 & 15) << 2;
            sK[(j4 + 0) * SP + tt] = kr[f].x;
            sK[(j4 + 1) * SP + tt] = kr[f].y;
            sK[(j4 + 2) * SP + tt] = kr[f].z;
            sK[(j4 + 3) * SP + tt] = kr[f].w;
        }
    }
    __syncthreads();

    // export normalized Q transposed [j][t] for phase 3
    #pragma unroll
    for (int f = 0; f < 4; f++) {
        const int e4 = f * 256 + tid;
        const int jj = e4 >> 4, t4 = (e4 & 15) << 2;
        *(float4*)&g_qn[(((size_t)bh * NC + tc) * 64 + jj) * 64 + t4] =
            *(const float4*)&sQ[jj * SP + t4];
    }

    // G[t][s] (causal) from Qt/Kt; overwrite sK with Gt[s][t]
    {
        const int t4 = (tid & 15) * 4, s4 = (tid >> 4) * 4;
        float acc[4][4];
        #pragma unroll
        for (int a = 0; a < 4; a++)
            #pragma unroll
            for (int c = 0; c < 4; c++) acc[a][c] = 0.f;
        if (s4 <= t4 + 3) {
            for (int j = 0; j < 64; j++) {
                const float4 qv = *(const float4*)&sQ[j * SP + t4];
                const float4 kv = *(const float4*)&sK[j * SP + s4];
                OP16(acc, qv, kv);
            }
        }
        __syncthreads();
        #pragma unroll
        for (int c = 0; c < 4; c++) {
            float4 o;
            o.x = (s4 + c <= t4 + 0) ? acc[0][c] : 0.f;
            o.y = (s4 + c <= t4 + 1) ? acc[1][c] : 0.f;
            o.z = (s4 + c <= t4 + 2) ? acc[2][c] : 0.f;
            o.w = (s4 + c <= t4 + 3) ? acc[3][c] : 0.f;
            *(float4*)&sK[(s4 + c) * SP + t4] = o;
        }
    }
    __syncthreads();

    // r_local[t][i] = sum_{s<=t} G[t][s] * A[s][i]; store es_t * r_local
    {
        const int t4 = (tid & 15) * 4, i4 = (tid >> 4) * 4;
        float acc[4][4];
        #pragma unroll
        for (int a = 0; a < 4; a++)
            #pragma unroll
            for (int c = 0; c < 4; c++) acc[a][c] = 0.f;
        const int smax = t4 + 4;
        for (int s = 0; s < smax; s++) {
            const float4 gv = *(const float4*)&sK[s * SP + t4];
            const float4 av = *(const float4*)&sA[s * SP + i4];
            OP16(acc, gv, av);
        }
        #pragma unroll
        for (int a = 0; a < 4; a++) {
            const float e = es[t4 + a];
            const size_t ro = (size_t)(b * NT + tc * 64 + t4 + a) * NHD + h * 64;
            #pragma unroll
            for (int c = 0; c < 4; c++) g_read[ro + i4 + c] = e * acc[a][c];
        }
    }
}

// ============ phase 2: exclusive prefix of chunk sums + next_mem ===========
__global__ __launch_bounds__(256) void scan_p2(float* __restrict__ next_mem) {
    const int bh = blockIdx.x;
    const int e  = blockIdx.y * 256 + threadIdx.x;      // 0..4095
    const float elast = g_ecum[bh * NT + NT - 1];
    float acc = 0.f;
    #pragma unroll
    for (int c = 0; c < NC; c++) {
        g_P[((size_t)bh * NC + c) * 4096 + e] = acc;
        acc += g_S[((size_t)bh * NC + c) * 4096 + e];
    }
    next_mem[(size_t)bh * 4096 + e] = acc * elast;
}

// ============ phase 3: cross term r += es_t * (P_{c-1} q_t) ================
__global__ __launch_bounds__(256) void scan_p3() {
    __shared__ float sQt[64 * SP];
    __shared__ float sPt[64 * SP];
    __shared__ float es[64];
    const int tc = blockIdx.x + 1, bh = blockIdx.y, b = bh >> 3, h = bh & 7;
    const int tid = threadIdx.x;
    #pragma unroll
    for (int f = 0; f < 4; f++) {
        const int e4 = f * 256 + tid;
        const int r = e4 >> 4, c4 = (e4 & 15) << 2;
        *(float4*)&sQt[r * SP + c4] =
            *(const float4*)&g_qn[(((size_t)bh * NC + tc) * 64 + r) * 64 + c4];
        const float4 p =
            *(const float4*)&g_P[((size_t)bh * NC + tc) * 4096 + r * 64 + c4];
        sPt[(c4 + 0) * SP + r] = p.x; sPt[(c4 + 1) * SP + r] = p.y;
        sPt[(c4 + 2) * SP + r] = p.z; sPt[(c4 + 3) * SP + r] = p.w;
    }
    if (tid < 64) es[tid] = g_ecum[bh * NT + tc * 64 + tid];
    __syncthreads();

    const int t4 = (tid & 15) * 4, i4 = (tid >> 4) * 4;
    float acc[4][4];
    #pragma unroll
    for (int a = 0; a < 4; a++)
        #pragma unroll
        for (int c = 0; c < 4; c++) acc[a][c] = 0.f;
    for (int j = 0; j < 64; j++) {
        const float4 qv = *(const float4*)&sQt[j * SP + t4];
        const float4 pv = *(const float4*)&sPt[j * SP + i4];
        OP16(acc, qv, pv);
    }
    #pragma unroll
    for (int a = 0; a < 4; a++) {
        const float e = es[t4 + a];
        const size_t ro = (size_t)(b * NT + tc * 64 + t4 + a) * NHD + h * 64;
        #pragma unroll
        for (int c = 0; c < 4; c++) g_read[ro + i4 + c] += e * acc[a][c];
    }
}

// ---------------------------------------------------------------- launch ---
static float* sym(const void* s) {
    void* p = nullptr;
    cudaGetSymbolAddress(&p, s);
    return (float*)p;
}

extern "C" void kernel_launch(void* const* d_in, const int* in_sizes, int n_in,
                              void* d_out, int out_size) {
    const float* x     = (const float*)d_in[0];
    const float* b_min = (const float*)d_in[1];
    const float* b_max = (const float*)d_in[2];
    const float* motif = (const float*)d_in[3];
    const float* Wk    = (const float*)d_in[4];
    const float* bk    = (const float*)d_in[5];
    const float* Wq    = (const float*)d_in[6];
    const float* bq    = (const float*)d_in[7];
    const float* Wv    = (const float*)d_in[8];
    const float* bv    = (const float*)d_in[9];
    const float* Wo    = (const float*)d_in[10];
    const float* bo    = (const float*)d_in[11];
    const float* Wd    = (const float*)d_in[12];
    const float* bd    = (const float*)d_in[13];
    const float* Wgw   = (const float*)d_in[14];
    const float* bgw   = (const float*)d_in[15];
    const float* Wgf   = (const float*)d_in[16];
    const float* bgf   = (const float*)d_in[17];
    const float* Wps   = (const float*)d_in[18];
    const float* bps   = (const float*)d_in[19];
    const float* ln1g  = (const float*)d_in[20];
    const float* ln1b  = (const float*)d_in[21];
    const float* ln2g  = (const float*)d_in[22];
    const float* ln2b  = (const float*)d_in[23];
    const float* W1    = (const float*)d_in[24];
    const float* b1    = (const float*)d_in[25];
    const float* W2    = (const float*)d_in[26];
    const float* b2    = (const float*)d_in[27];

    float* out    = (float*)d_out;
    float* out_x3 = out;                            // [2,1024,512]
    float* out_nm = out + (size_t)NROWS * NE;       // [2,8,64,64]
    float* out_pm = out_nm + NBH * ND * ND;         // b_min + probe
    float* out_px = out_pm + (size_t)NROWS * NE;    // b_max + probe

    float* xn   = sym(g_xn);
    float* WT1  = sym(g_WT1);
    float* WoT  = sym(g_WoT);
    float* W1T  = sym(g_W1T);
    float* W2T  = sym(g_W2T);
    float* WpsT = sym(g_WpsT);
    float* bkqv = sym(g_bkqv);
    float* kqv  = sym(g_kqv);
    float* rd   = sym(g_read);
    float* x2   = sym(g_x2);
    float* hh   = sym(g_hh);
    float* mid  = sym(g_mid);

    const int SM128 = 3 * (128 * KP2 + 128 * KP2) * 4;   // 110592
    const int SM64  = 3 * (128 * KP2 + 64 * KP2)  * 4;   // 82944
    const int SMP1  = (3 * 64 * SP + 64) * 4;            // 52480
    cudaFuncSetAttribute(tgemm_k<5,128,128>, cudaFuncAttributeMaxDynamicSharedMemorySize, SM128);
    cudaFuncSetAttribute(tgemm_k<2,128,128>, cudaFuncAttributeMaxDynamicSharedMemorySize, SM128);
    cudaFuncSetAttribute(tgemm_k<1,64,128>,  cudaFuncAttributeMaxDynamicSharedMemorySize, SM64);
    cudaFuncSetAttribute(tgemm_k<3,64,128>,  cudaFuncAttributeMaxDynamicSharedMemorySize, SM64);
    cudaFuncSetAttribute(tgemm_k<4,64,128>,  cudaFuncAttributeMaxDynamicSharedMemorySize, SM64);
    cudaFuncSetAttribute(scan_p1,            cudaFuncAttributeMaxDynamicSharedMemorySize, SMP1);

    // fused: LN1 + WT1 transposes + bias/zero (critical-path minimum)
    const int ZB_BLOCKS = (104 * NE + 255) / 256;        // 208
    ln_prep_k<<<NROWS + WT1_BLOCKS + ZB_BLOCKS, 256>>>(
        x, ln1g, ln1b, Wk, Wq, Wv, Wd, Wgw, Wgf,
        bk, bq, bv, bd, bgw, bgf);                                             // 0
    tgemm_k<5,128,128><<<dim3(13, 16), 256, SM128>>>(xn, WT1, bkqv, kqv,
                                                     512, LDW,
                                                     nullptr, nullptr, nullptr);// 1
    // cumsum + big-weight transposes sharing one launch (chip otherwise idle)
    cumsum_k<<<NBH + XT_BLOCKS, 256>>>(Wo, W1, W2, Wps);                       // 2
    scan_p1<<<dim3(NC, NBH), 256, SMP1>>>();                                   // 3
    scan_p2<<<dim3(NBH, 16), 256>>>(out_nm);                                   // 4
    scan_p3<<<dim3(NC - 1, NBH), 256>>>();                                     // 5

    tgemm_k<1,64,128><<<dim3(8, 16), 256, SM64>>>(rd, WoT, bo, x2, 512, 512,
                                                  x, motif, nullptr);          // 6
    ln_k<<<NROWS, 256>>>(x2, ln2g, ln2b, hh);                                  // 7
    tgemm_k<2,128,128><<<dim3(16, 16), 256, SM128>>>(hh, W1T, b1, mid,
                                                     512, 2048,
                                                     nullptr, nullptr, nullptr);// 8
    tgemm_k<3,64,128><<<dim3(8, 16), 256, SM64>>>(mid, W2T, b2, out_x3,
                                                  2048, 512,
                                                  x2, nullptr, nullptr);       // 9
    tgemm_k<4,64,128><<<dim3(8, 16), 256, SM64>>>(out_x3, WpsT, bps, out_pm,
                                                  512, 512,
                                                  b_min, b_max, out_px);       // 10
}